// round 2
// baseline (speedup 1.0000x reference)
#include <cuda_runtime.h>
#include <cstdint>
#include <cstddef>

#define SEQ   512
#define BATCH 64
#define HS    1024
#define NG    4096            // 4*HS
#define MROWS (SEQ*BATCH)     // 32768
#define KSPLIT 8
#define NB_PERS 128           // persistent grid size (<=148 SMs -> co-resident)

typedef unsigned long long u64;

// ---------------- static device scratch (no allocations allowed) ----------------
__device__ float g_pre[(size_t)SEQ * BATCH * NG];    // input projection + bias, current layer
__device__ float g_out0[(size_t)SEQ * BATCH * HS];   // layer0 outputs
__device__ float g_part[KSPLIT * BATCH * NG];        // split-K partials for recurrent gemm
__device__ float g_h[BATCH * HS];

// ---------------- self-resetting grid barrier (graph-replay safe) ---------------
__device__ unsigned g_cnt = 0;
__device__ volatile unsigned g_gen = 0;

__device__ __forceinline__ void grid_barrier() {
    __syncthreads();
    if (threadIdx.x == 0) {
        __threadfence();
        unsigned mygen = g_gen;
        if (atomicAdd(&g_cnt, 1u) == (unsigned)(NB_PERS - 1)) {
            g_cnt = 0;
            __threadfence();
            atomicAdd((unsigned*)&g_gen, 1u);   // monotonic generation; never reset
        } else {
            while (g_gen == mygen) { __nanosleep(32); }
        }
    }
    __syncthreads();
}

// ---------------- packed fp32x2 FMA helpers (full-rate FFMA2 on sm_103a) --------
__device__ __forceinline__ void ffma2(u64& d, u64 a, u64 b) {
    asm("fma.rn.f32x2 %0, %1, %2, %0;" : "+l"(d) : "l"(a), "l"(b));
}
__device__ __forceinline__ u64 pack2(float x) {
    u64 r; asm("mov.b64 %0, {%1, %1};" : "=l"(r) : "f"(x)); return r;
}
__device__ __forceinline__ float2 unpack2(u64 v) {
    float2 r; asm("mov.b64 {%0, %1}, %2;" : "=f"(r.x), "=f"(r.y) : "l"(v)); return r;
}

// accurate activations (avoid tanh.approx: 2^-11 err too coarse for 512 steps)
__device__ __forceinline__ float sigmoid_acc(float x) {
    return 1.0f / (1.0f + __expf(-x));
}
__device__ __forceinline__ float tanh_acc(float x) {
    float e = __expf(-2.0f * fabsf(x));
    float t = (1.0f - e) / (1.0f + e);
    return copysignf(t, x);
}

// =================================================================================
// Input projection GEMM: C[M, NG] = A[M,1024] * W[NG,1024]^T + (b1 + b2)
// Tiles 128x128x16, 256 threads, 8x8 microtile, col-pair packed FFMA2.
// =================================================================================
__global__ __launch_bounds__(256) void k_inproj(
    const float* __restrict__ A, const float* __restrict__ W,
    const float* __restrict__ b1, const float* __restrict__ b2,
    float* __restrict__ C)
{
    __shared__ float As[16][128];
    __shared__ float Bs[16][128];

    const int tid = threadIdx.x;
    const int m0  = blockIdx.y * 128;
    const int n0  = blockIdx.x * 128;
    const int lr  = tid >> 1;            // load row 0..127
    const int lk  = (tid & 1) * 8;       // k offset 0 or 8
    const int tr  = tid >> 4;            // 0..15 (rows tr*8..tr*8+7)
    const int tc  = tid & 15;            // 0..15 (cols tc*4..+3 and 64+tc*4..+3)

    u64 acc[8][4];
#pragma unroll
    for (int i = 0; i < 8; i++)
#pragma unroll
        for (int j = 0; j < 4; j++) acc[i][j] = 0ull;

    const float* Ap = A + (size_t)(m0 + lr) * 1024 + lk;
    const float* Wp = W + (size_t)(n0 + lr) * 1024 + lk;

    for (int k0 = 0; k0 < 1024; k0 += 16) {
        float4 a0 = *reinterpret_cast<const float4*>(Ap + k0);
        float4 a1 = *reinterpret_cast<const float4*>(Ap + k0 + 4);
        float4 w0 = *reinterpret_cast<const float4*>(Wp + k0);
        float4 w1 = *reinterpret_cast<const float4*>(Wp + k0 + 4);
        As[lk+0][lr]=a0.x; As[lk+1][lr]=a0.y; As[lk+2][lr]=a0.z; As[lk+3][lr]=a0.w;
        As[lk+4][lr]=a1.x; As[lk+5][lr]=a1.y; As[lk+6][lr]=a1.z; As[lk+7][lr]=a1.w;
        Bs[lk+0][lr]=w0.x; Bs[lk+1][lr]=w0.y; Bs[lk+2][lr]=w0.z; Bs[lk+3][lr]=w0.w;
        Bs[lk+4][lr]=w1.x; Bs[lk+5][lr]=w1.y; Bs[lk+6][lr]=w1.z; Bs[lk+7][lr]=w1.w;
        __syncthreads();

#pragma unroll
        for (int kk = 0; kk < 16; kk++) {
            union { float4 f4; u64 u2[2]; } vb0, vb1;
            vb0.f4 = *reinterpret_cast<const float4*>(&Bs[kk][tc * 4]);
            vb1.f4 = *reinterpret_cast<const float4*>(&Bs[kk][64 + tc * 4]);
            const u64 rb0 = vb0.u2[0], rb1 = vb0.u2[1];
            const u64 rb2 = vb1.u2[0], rb3 = vb1.u2[1];
#pragma unroll
            for (int i = 0; i < 8; i++) {
                u64 a2 = pack2(As[kk][tr * 8 + i]);
                ffma2(acc[i][0], a2, rb0);
                ffma2(acc[i][1], a2, rb1);
                ffma2(acc[i][2], a2, rb2);
                ffma2(acc[i][3], a2, rb3);
            }
        }
        __syncthreads();
    }

    // bias (bih + bhh)
    float4 x1 = *reinterpret_cast<const float4*>(&b1[n0 + tc * 4]);
    float4 x2 = *reinterpret_cast<const float4*>(&b2[n0 + tc * 4]);
    float4 y1 = *reinterpret_cast<const float4*>(&b1[n0 + 64 + tc * 4]);
    float4 y2 = *reinterpret_cast<const float4*>(&b2[n0 + 64 + tc * 4]);
    const float4 bias0 = make_float4(x1.x+x2.x, x1.y+x2.y, x1.z+x2.z, x1.w+x2.w);
    const float4 bias1 = make_float4(y1.x+y2.x, y1.y+y2.y, y1.z+y2.z, y1.w+y2.w);

#pragma unroll
    for (int i = 0; i < 8; i++) {
        const size_t row = (size_t)(m0 + tr * 8 + i);
        float2 p0 = unpack2(acc[i][0]), p1 = unpack2(acc[i][1]);
        float2 p2 = unpack2(acc[i][2]), p3 = unpack2(acc[i][3]);
        float4 o0 = make_float4(p0.x+bias0.x, p0.y+bias0.y, p1.x+bias0.z, p1.y+bias0.w);
        float4 o1 = make_float4(p2.x+bias1.x, p2.y+bias1.y, p3.x+bias1.z, p3.y+bias1.w);
        *reinterpret_cast<float4*>(&C[row * NG + n0 + tc * 4])      = o0;
        *reinterpret_cast<float4*>(&C[row * NG + n0 + 64 + tc * 4]) = o1;
    }
}

// =================================================================================
// Persistent LSTM layer kernel: runs all SEQ timesteps.
// grid = 128 CTAs: bx&15 -> n-tile (256 cols), bx>>4 -> k-chunk (128).
// Per step: phase A = recurrent GEMM (split-K partials to g_part, L2-scope),
//           barrier, phase B = pointwise (gate reduce + activations), barrier.
// c lives in registers for the whole sequence; h goes through L2 (__stcg/__ldcg).
// =================================================================================
__global__ __launch_bounds__(256) void k_layer(
    const float* __restrict__ V, const float* __restrict__ pre,
    float* __restrict__ outbuf, float* __restrict__ dh, float* __restrict__ dc)
{
    __shared__ float Hs[16][64];
    __shared__ float Vs[16][256];

    const int tid = threadIdx.x;
    const int bx  = blockIdx.x;
    const int n0  = (bx & 15) * 256;
    const int k0  = (bx >> 4) * 128;
    const int tr  = tid >> 5;            // 0..7 (rows tr*8..+7)
    const int tc  = tid & 31;            // 0..31

    // pointwise mapping: this thread owns elements (b, j2) and (b, j2+1)
    const int g  = bx * 256 + tid;       // 0..32767
    const int pb = g >> 9;               // batch 0..63
    const int j2 = (g & 511) * 2;        // even col 0..1022

    const int hr = tid >> 2;             // 0..63
    const int hk = (tid & 3) * 4;        // 0,4,8,12
    const float* vp_base = V + (size_t)(n0 + tid) * HS + k0;
    float* part_dst = g_part + (size_t)(bx >> 4) * (BATCH * NG) + n0;

    // init: zero h (c kept in regs)
    float2 c2 = make_float2(0.0f, 0.0f);
    float2 h2 = make_float2(0.0f, 0.0f);
    __stcg(reinterpret_cast<float2*>(&g_h[pb * HS + j2]), h2);
    grid_barrier();

    for (int t = 0; t < SEQ; t++) {
        // ---------------- phase A: partial GEMM  part[b][n] = sum_k h[b,k]*V[n,k]
        u64 acc[8][4];
#pragma unroll
        for (int i = 0; i < 8; i++)
#pragma unroll
            for (int j = 0; j < 4; j++) acc[i][j] = 0ull;

        for (int kb = 0; kb < 128; kb += 16) {
            float4 hv = __ldcg(reinterpret_cast<const float4*>(&g_h[hr * HS + k0 + kb + hk]));
            Hs[hk+0][hr]=hv.x; Hs[hk+1][hr]=hv.y; Hs[hk+2][hr]=hv.z; Hs[hk+3][hr]=hv.w;
#pragma unroll
            for (int q = 0; q < 4; q++) {
                float4 vv = *reinterpret_cast<const float4*>(vp_base + kb + q * 4);
                Vs[q*4+0][tid]=vv.x; Vs[q*4+1][tid]=vv.y; Vs[q*4+2][tid]=vv.z; Vs[q*4+3][tid]=vv.w;
            }
            __syncthreads();

#pragma unroll
            for (int kk = 0; kk < 16; kk++) {
                union { float4 f4; u64 u2[2]; } v0, v1;
                v0.f4 = *reinterpret_cast<const float4*>(&Vs[kk][tc * 4]);
                v1.f4 = *reinterpret_cast<const float4*>(&Vs[kk][128 + tc * 4]);
                const u64 rb0 = v0.u2[0], rb1 = v0.u2[1];
                const u64 rb2 = v1.u2[0], rb3 = v1.u2[1];
#pragma unroll
                for (int i = 0; i < 8; i++) {
                    u64 a2 = pack2(Hs[kk][tr * 8 + i]);
                    ffma2(acc[i][0], a2, rb0);
                    ffma2(acc[i][1], a2, rb1);
                    ffma2(acc[i][2], a2, rb2);
                    ffma2(acc[i][3], a2, rb3);
                }
            }
            __syncthreads();
        }

#pragma unroll
        for (int i = 0; i < 8; i++) {
            const size_t row = (size_t)(tr * 8 + i);
            float2 p0 = unpack2(acc[i][0]), p1 = unpack2(acc[i][1]);
            float2 p2 = unpack2(acc[i][2]), p3 = unpack2(acc[i][3]);
            __stcg(reinterpret_cast<float4*>(&part_dst[row * NG + tc * 4]),
                   make_float4(p0.x,p0.y,p1.x,p1.y));
            __stcg(reinterpret_cast<float4*>(&part_dst[row * NG + 128 + tc * 4]),
                   make_float4(p2.x,p2.y,p3.x,p3.y));
        }

        grid_barrier();

        // ---------------- phase B: pointwise gate update (2 elems/thread)
        const float* pr = pre + (size_t)t * (BATCH * NG) + (size_t)pb * NG + j2;
        float2 gi = *reinterpret_cast<const float2*>(pr);
        float2 gf = *reinterpret_cast<const float2*>(pr + 1024);
        float2 gg = *reinterpret_cast<const float2*>(pr + 2048);
        float2 go = *reinterpret_cast<const float2*>(pr + 3072);
#pragma unroll
        for (int ks = 0; ks < KSPLIT; ks++) {
            const float* pp = g_part + (size_t)ks * (BATCH * NG) + (size_t)pb * NG + j2;
            float2 a = __ldcg(reinterpret_cast<const float2*>(pp));
            float2 b = __ldcg(reinterpret_cast<const float2*>(pp + 1024));
            float2 cgate = __ldcg(reinterpret_cast<const float2*>(pp + 2048));
            float2 d = __ldcg(reinterpret_cast<const float2*>(pp + 3072));
            gi.x += a.x; gi.y += a.y; gf.x += b.x; gf.y += b.y;
            gg.x += cgate.x; gg.y += cgate.y; go.x += d.x; go.y += d.y;
        }
        {
            float iv = sigmoid_acc(gi.x), fv = sigmoid_acc(gf.x);
            float gv = tanh_acc(gg.x),   ov = sigmoid_acc(go.x);
            c2.x = fv * c2.x + iv * gv;
            h2.x = ov * tanh_acc(c2.x);
        }
        {
            float iv = sigmoid_acc(gi.y), fv = sigmoid_acc(gf.y);
            float gv = tanh_acc(gg.y),   ov = sigmoid_acc(go.y);
            c2.y = fv * c2.y + iv * gv;
            h2.y = ov * tanh_acc(c2.y);
        }
        __stcg(reinterpret_cast<float2*>(&g_h[pb * HS + j2]), h2);
        *reinterpret_cast<float2*>(&outbuf[(size_t)t * (BATCH * HS) + pb * HS + j2]) = h2;

        grid_barrier();
    }

    // final h/c dump (own elements, values live in registers)
    *reinterpret_cast<float2*>(&dh[pb * HS + j2]) = h2;
    *reinterpret_cast<float2*>(&dc[pb * HS + j2]) = c2;
}

// =================================================================================
extern "C" void kernel_launch(void* const* d_in, const int* in_sizes, int n_in,
                              void* d_out, int out_size)
{
    const float* x   = (const float*)d_in[0];
    const float* U0  = (const float*)d_in[1];
    const float* V0  = (const float*)d_in[2];
    const float* bi0 = (const float*)d_in[3];
    const float* bh0 = (const float*)d_in[4];
    const float* U1  = (const float*)d_in[5];
    const float* V1  = (const float*)d_in[6];
    const float* bi1 = (const float*)d_in[7];
    const float* bh1 = (const float*)d_in[8];
    float* out = (float*)d_out;

    float *pre = nullptr, *out0 = nullptr;
    cudaGetSymbolAddress((void**)&pre,  g_pre);
    cudaGetSymbolAddress((void**)&out0, g_out0);

    const dim3 gIn(NG / 128, MROWS / 128);  // (32, 256)

    const size_t O_OUT = (size_t)SEQ * BATCH * HS;   // 33,554,432
    const size_t BH    = (size_t)BATCH * HS;         // 65,536

    // layer 0
    k_inproj<<<gIn, 256>>>(x, U0, bi0, bh0, pre);
    k_layer<<<NB_PERS, 256>>>(V0, pre, out0,
                              out + O_OUT,          // h_f[0]
                              out + O_OUT + 2 * BH);// c_f[0]

    // layer 1
    k_inproj<<<gIn, 256>>>(out0, U1, bi1, bh1, pre);
    k_layer<<<NB_PERS, 256>>>(V1, pre, out,
                              out + O_OUT + BH,     // h_f[1]
                              out + O_OUT + 3 * BH);// c_f[1]
}

// round 4
// speedup vs baseline: 1.6223x; 1.6223x over previous
#include <cuda_runtime.h>
#include <cuda_bf16.h>
#include <cstdint>
#include <cstddef>

#define SEQ   512
#define BATCH 64
#define HS    1024
#define NG    4096
#define MROWS (SEQ*BATCH)     // 32768
#define KSPLIT 4
#define NB_PERS 128
#define SMEM_LAYER (192*1024 + 1024)
#define SMEM_INPROJ (64*1024 + 1024)

typedef unsigned long long u64;
typedef __nv_bfloat16 bf16;

// ---------------- static device scratch ----------------
__device__ float g_pre[(size_t)MROWS * NG];          // gate pre-activations (current layer)
__device__ bf16  g_xs[(size_t)MROWS * 2 * HS];       // input splits (hi|lo), also layer0 output splits
__device__ bf16  g_hs[BATCH * 2 * HS];               // h splits (hi|lo)
__device__ bf16  g_Us0[(size_t)NG * 2 * HS];
__device__ bf16  g_Vs0[(size_t)NG * 2 * HS];
__device__ bf16  g_Us1[(size_t)NG * 2 * HS];
__device__ bf16  g_Vs1[(size_t)NG * 2 * HS];
__device__ float g_part[KSPLIT * BATCH * NG];        // split-K partials

// ---------------- grid barrier (graph-replay safe, monotonic generation) --------
__device__ unsigned g_cnt = 0;
__device__ volatile unsigned g_gen = 0;

__device__ __forceinline__ void grid_barrier() {
    __threadfence();
    __syncthreads();
    if (threadIdx.x == 0) {
        unsigned mygen = g_gen;
        if (atomicAdd(&g_cnt, 1u) == (unsigned)(NB_PERS - 1)) {
            g_cnt = 0;
            __threadfence();
            atomicAdd((unsigned*)&g_gen, 1u);
        } else {
            while (g_gen == mygen) { __nanosleep(32); }
        }
    }
    __syncthreads();
}

// ---------------- mma.sync building blocks ----------------
__device__ __forceinline__ uint32_t smem_u32(const void* p) {
    uint32_t a;
    asm("{ .reg .u64 t; cvta.to.shared.u64 t, %1; cvt.u32.u64 %0, t; }" : "=r"(a) : "l"(p));
    return a;
}
__device__ __forceinline__ void ldsm4(uint32_t* f, uint32_t addr) {
    asm volatile("ldmatrix.sync.aligned.m8n8.x4.shared.b16 {%0,%1,%2,%3}, [%4];"
        : "=r"(f[0]), "=r"(f[1]), "=r"(f[2]), "=r"(f[3]) : "r"(addr));
}
__device__ __forceinline__ void mma16816(float* d, const uint32_t* a, uint32_t b0, uint32_t b1) {
    asm volatile("mma.sync.aligned.m16n8k16.row.col.f32.bf16.bf16.f32 "
        "{%0,%1,%2,%3}, {%4,%5,%6,%7}, {%8,%9}, {%0,%1,%2,%3};"
        : "+f"(d[0]), "+f"(d[1]), "+f"(d[2]), "+f"(d[3])
        : "r"(a[0]), "r"(a[1]), "r"(a[2]), "r"(a[3]), "r"(b0), "r"(b1));
}
// swizzled byte offset inside a [rows x 64 bf16] tile (128B rows)
__device__ __forceinline__ uint32_t swz(uint32_t r, uint32_t c16) {
    return r * 128u + ((c16 ^ (r & 7u)) << 4);
}
// A-fragment ldmatrix address (m16 x k16 at (m0, k0) in tile)
__device__ __forceinline__ uint32_t a_addr(uint32_t base, int lane, int m0, int k0) {
    int sel = lane >> 3;
    uint32_t row = (uint32_t)(m0 + (lane & 7) + ((sel & 1) << 3));
    uint32_t c16 = (uint32_t)((k0 >> 3) + (sel >> 1));
    return base + swz(row, c16);
}
// B-fragment ldmatrix address (n16 x k16 at (n0, k0)): f0,f1 = n-tile0, f2,f3 = n-tile1
__device__ __forceinline__ uint32_t b_addr(uint32_t base, int lane, int n0, int k0) {
    int sel = lane >> 3;
    uint32_t row = (uint32_t)(n0 + (lane & 7) + ((sel >> 1) << 3));
    uint32_t c16 = (uint32_t)((k0 >> 3) + (sel & 1));
    return base + swz(row, c16);
}

// load a [rows x 64] bf16 tile (row stride ld elems) into swizzled smem tile
template <bool BYPASS_L1>
__device__ __forceinline__ void load_tile(uint32_t sdst, const bf16* __restrict__ src,
                                          int rows, int ld) {
    const int chunks = rows * 8;                   // 16B chunks
    for (int i = threadIdx.x; i < chunks; i += 256) {
        int r = i >> 3, c = i & 7;
        const uint4* p = reinterpret_cast<const uint4*>(src + (size_t)r * ld + c * 8);
        uint4 v = BYPASS_L1 ? __ldcg(p) : __ldg(p);
        asm volatile("st.shared.v4.b32 [%0], {%1,%2,%3,%4};"
                     :: "r"(sdst + swz((uint32_t)r, (uint32_t)c)),
                        "r"(v.x), "r"(v.y), "r"(v.z), "r"(v.w));
    }
}

// ---------------- activations (accurate) ----------------
__device__ __forceinline__ float sigmoid_acc(float x) {
    return 1.0f / (1.0f + __expf(-x));
}
__device__ __forceinline__ float tanh_acc(float x) {
    float e = __expf(-2.0f * fabsf(x));
    float t = (1.0f - e) / (1.0f + e);
    return copysignf(t, x);
}
__device__ __forceinline__ void split2(float v, bf16& hi, bf16& lo) {
    hi = __float2bfloat16(v);
    lo = __float2bfloat16(v - __bfloat162float(hi));
}

// =================================================================================
// split kernels
// =================================================================================
__global__ __launch_bounds__(256) void k_split_x(const float* __restrict__ x) {
    size_t i = (size_t)blockIdx.x * 256 + threadIdx.x;
    size_t m = i >> 10, k = i & 1023;
    bf16 hi, lo; split2(x[i], hi, lo);
    g_xs[m * 2048 + k]        = hi;
    g_xs[m * 2048 + 1024 + k] = lo;
}
__global__ __launch_bounds__(256) void k_split_w(const float* __restrict__ W, bf16* __restrict__ dst) {
    size_t i = (size_t)blockIdx.x * 256 + threadIdx.x;
    size_t n = i >> 10, k = i & 1023;
    bf16 hi, lo; split2(W[i], hi, lo);
    dst[n * 2048 + k]        = hi;
    dst[n * 2048 + 1024 + k] = lo;
}

// =================================================================================
// Input projection (HMMA): C[128m,128n] tile = [xhi|xlo] @ [Whi|Wlo]^T + b1 + b2
// 3-term compensated. 8 warps = 4m x 2n; warp tile 32m x 64n.
// =================================================================================
__global__ __launch_bounds__(256, 2) void k_inproj_t(
    const bf16* __restrict__ A, const bf16* __restrict__ W,
    const float* __restrict__ b1, const float* __restrict__ b2,
    float* __restrict__ C)
{
    extern __shared__ char dsm[];
    const uint32_t sbase = (smem_u32(dsm) + 1023u) & ~1023u;
    const uint32_t sAh = sbase, sAl = sbase + 16384, sBh = sbase + 32768, sBl = sbase + 49152;
    const int tid = threadIdx.x, wid = tid >> 5, lane = tid & 31;
    const int m0 = blockIdx.y * 128, n0 = blockIdx.x * 128;
    const int mi = wid & 3, ni = wid >> 2;

    float acc[2][8][4];
#pragma unroll
    for (int a = 0; a < 2; a++)
#pragma unroll
        for (int b = 0; b < 8; b++)
#pragma unroll
            for (int cpos = 0; cpos < 4; cpos++) acc[a][b][cpos] = 0.f;

    const bf16* Arow = A + (size_t)m0 * 2048;
    const bf16* Wrow = W + (size_t)n0 * 2048;

    for (int kb = 0; kb < 16; kb++) {
        const int k0g = kb * 64;
        load_tile<false>(sAh, Arow + k0g,        128, 2048);
        load_tile<false>(sAl, Arow + 1024 + k0g, 128, 2048);
        load_tile<false>(sBh, Wrow + k0g,        128, 2048);
        load_tile<false>(sBl, Wrow + 1024 + k0g, 128, 2048);
        __syncthreads();

#pragma unroll
        for (int ks = 0; ks < 4; ks++) {
            const int k0 = ks * 16;
            uint32_t ah[2][4], al[2][4];
#pragma unroll
            for (int mf = 0; mf < 2; mf++) {
                ldsm4(ah[mf], a_addr(sAh, lane, mi * 32 + mf * 16, k0));
                ldsm4(al[mf], a_addr(sAl, lane, mi * 32 + mf * 16, k0));
            }
#pragma unroll
            for (int np = 0; np < 4; np++) {
                const int nt = ni * 64 + np * 16;
                uint32_t bh[4], bl[4];
                ldsm4(bh, b_addr(sBh, lane, nt, k0));
#pragma unroll
                for (int mf = 0; mf < 2; mf++) {
                    mma16816(acc[mf][np * 2],     ah[mf], bh[0], bh[1]);
                    mma16816(acc[mf][np * 2 + 1], ah[mf], bh[2], bh[3]);
                    mma16816(acc[mf][np * 2],     al[mf], bh[0], bh[1]);
                    mma16816(acc[mf][np * 2 + 1], al[mf], bh[2], bh[3]);
                }
                ldsm4(bl, b_addr(sBl, lane, nt, k0));
#pragma unroll
                for (int mf = 0; mf < 2; mf++) {
                    mma16816(acc[mf][np * 2],     ah[mf], bl[0], bl[1]);
                    mma16816(acc[mf][np * 2 + 1], ah[mf], bl[2], bl[3]);
                }
            }
        }
        __syncthreads();
    }

    // epilogue: D frags -> C with bias
    const int r = lane >> 2, cq = (lane & 3) * 2;
#pragma unroll
    for (int mf = 0; mf < 2; mf++) {
#pragma unroll
        for (int nf = 0; nf < 8; nf++) {
            const int ncol = n0 + ni * 64 + nf * 8 + cq;
            const float bb0 = __ldg(b1 + ncol)     + __ldg(b2 + ncol);
            const float bb1 = __ldg(b1 + ncol + 1) + __ldg(b2 + ncol + 1);
            const int row0 = m0 + mi * 32 + mf * 16 + r;
            float2 v0 = make_float2(acc[mf][nf][0] + bb0, acc[mf][nf][1] + bb1);
            float2 v1 = make_float2(acc[mf][nf][2] + bb0, acc[mf][nf][3] + bb1);
            *reinterpret_cast<float2*>(C + (size_t)row0 * NG + ncol)       = v0;
            *reinterpret_cast<float2*>(C + (size_t)(row0 + 8) * NG + ncol) = v1;
        }
    }
}

// =================================================================================
// Persistent LSTM layer (HMMA recurrent GEMM, V resident in smem).
// grid = 128 CTAs: n-tile = (bx&31)*128, K-split ks = bx>>5 (256 k-cols).
// smem: V [2 splits][4 kblocks][128x64] = 128KB, A(h) [2][4][64x64] = 64KB.
// 8 warps = 4m x 2n; warp tile 16m x 64n (M=64 batch).
// =================================================================================
__global__ __launch_bounds__(256) void k_layer_t(
    const bf16* __restrict__ Vs, const float* __restrict__ pre,
    float* __restrict__ outbuf, bf16* __restrict__ xsplit,
    float* __restrict__ dh, float* __restrict__ dc)
{
    extern __shared__ char dsm[];
    const uint32_t sbase = (smem_u32(dsm) + 1023u) & ~1023u;
    // V tile (s, kb): 16KB each; A tile (s, kb): 8KB each
    const uint32_t sV0 = sbase;                 // + (s*4+kb)*16384
    const uint32_t sA0 = sbase + 131072;        // + (s*4+kb)*8192
    const int tid = threadIdx.x, wid = tid >> 5, lane = tid & 31;
    const int bx = blockIdx.x;
    const int n0 = (bx & 31) * 128;
    const int ks = bx >> 5;
    const int kbase = ks * 256;
    const int mi = wid & 3, ni = wid >> 2;

    // pointwise mapping: this thread owns (pb, j2), (pb, j2+1)
    const int g = bx * 256 + tid;
    const int pb = g >> 9;
    const int j2 = (g & 511) * 2;

    // prologue: V slice resident in smem (hi+lo, 4 kblocks)
    for (int s = 0; s < 2; s++)
        for (int kb = 0; kb < 4; kb++)
            load_tile<false>(sV0 + (uint32_t)(s * 4 + kb) * 16384u,
                             Vs + (size_t)n0 * 2048 + s * 1024 + kbase + kb * 64,
                             128, 2048);

    float2 c2 = make_float2(0.f, 0.f), h2 = make_float2(0.f, 0.f);
    __stcg(reinterpret_cast<unsigned*>(g_hs + pb * 2048 + j2), 0u);
    __stcg(reinterpret_cast<unsigned*>(g_hs + pb * 2048 + 1024 + j2), 0u);
    grid_barrier();

    for (int t = 0; t < SEQ; t++) {
        // load h tiles (cross-SM: bypass L1)
        for (int s = 0; s < 2; s++)
            for (int kb = 0; kb < 4; kb++)
                load_tile<true>(sA0 + (uint32_t)(s * 4 + kb) * 8192u,
                                g_hs + s * 1024 + kbase + kb * 64,
                                64, 2048);
        __syncthreads();

        float acc[8][4];
#pragma unroll
        for (int b = 0; b < 8; b++)
#pragma unroll
            for (int cpos = 0; cpos < 4; cpos++) acc[b][cpos] = 0.f;

#pragma unroll 1
        for (int kb = 0; kb < 4; kb++) {
            const uint32_t vh = sV0 + (uint32_t)kb * 16384u;
            const uint32_t vl = sV0 + (uint32_t)(4 + kb) * 16384u;
            const uint32_t ahb = sA0 + (uint32_t)kb * 8192u;
            const uint32_t alb = sA0 + (uint32_t)(4 + kb) * 8192u;
#pragma unroll
            for (int kst = 0; kst < 4; kst++) {
                const int k0 = kst * 16;
                uint32_t ah[4], al[4];
                ldsm4(ah, a_addr(ahb, lane, mi * 16, k0));
                ldsm4(al, a_addr(alb, lane, mi * 16, k0));
#pragma unroll
                for (int np = 0; np < 4; np++) {
                    const int nt = ni * 64 + np * 16;
                    uint32_t bh[4], bl[4];
                    ldsm4(bh, b_addr(vh, lane, nt, k0));
                    mma16816(acc[np * 2],     ah, bh[0], bh[1]);
                    mma16816(acc[np * 2 + 1], ah, bh[2], bh[3]);
                    mma16816(acc[np * 2],     al, bh[0], bh[1]);
                    mma16816(acc[np * 2 + 1], al, bh[2], bh[3]);
                    ldsm4(bl, b_addr(vl, lane, nt, k0));
                    mma16816(acc[np * 2],     ah, bl[0], bl[1]);
                    mma16816(acc[np * 2 + 1], ah, bl[2], bl[3]);
                }
            }
        }

        // epilogue: partials -> g_part[ks][batch][n]
        {
            const int r = lane >> 2, cq = (lane & 3) * 2;
#pragma unroll
            for (int nf = 0; nf < 8; nf++) {
                const int ncol = n0 + ni * 64 + nf * 8 + cq;
                const int row0 = mi * 16 + r;
                float* dst0 = g_part + ((size_t)ks * BATCH + row0) * NG + ncol;
                float* dst1 = g_part + ((size_t)ks * BATCH + row0 + 8) * NG + ncol;
                __stcg(reinterpret_cast<float2*>(dst0), make_float2(acc[nf][0], acc[nf][1]));
                __stcg(reinterpret_cast<float2*>(dst1), make_float2(acc[nf][2], acc[nf][3]));
            }
        }
        grid_barrier();

        // pointwise: gate reduce + activations (2 elems/thread)
        const float* pr = pre + (size_t)t * (BATCH * NG) + (size_t)pb * NG + j2;
        float2 gi = *reinterpret_cast<const float2*>(pr);
        float2 gf = *reinterpret_cast<const float2*>(pr + 1024);
        float2 gg = *reinterpret_cast<const float2*>(pr + 2048);
        float2 go = *reinterpret_cast<const float2*>(pr + 3072);
#pragma unroll
        for (int s = 0; s < KSPLIT; s++) {
            const float* pp = g_part + (size_t)s * (BATCH * NG) + (size_t)pb * NG + j2;
            float2 a = __ldcg(reinterpret_cast<const float2*>(pp));
            float2 b = __ldcg(reinterpret_cast<const float2*>(pp + 1024));
            float2 cg = __ldcg(reinterpret_cast<const float2*>(pp + 2048));
            float2 d = __ldcg(reinterpret_cast<const float2*>(pp + 3072));
            gi.x += a.x;  gi.y += a.y;  gf.x += b.x;  gf.y += b.y;
            gg.x += cg.x; gg.y += cg.y; go.x += d.x;  go.y += d.y;
        }
        {
            float iv = sigmoid_acc(gi.x), fv = sigmoid_acc(gf.x);
            float gv = tanh_acc(gg.x),    ov = sigmoid_acc(go.x);
            c2.x = fv * c2.x + iv * gv;
            h2.x = ov * tanh_acc(c2.x);
        }
        {
            float iv = sigmoid_acc(gi.y), fv = sigmoid_acc(gf.y);
            float gv = tanh_acc(gg.y),    ov = sigmoid_acc(go.y);
            c2.y = fv * c2.y + iv * gv;
            h2.y = ov * tanh_acc(c2.y);
        }
        if (outbuf)
            *reinterpret_cast<float2*>(outbuf + (size_t)t * (BATCH * HS) + pb * HS + j2) = h2;

        bf16 xh, xl, yh, yl;
        split2(h2.x, xh, xl);
        split2(h2.y, yh, yl);
        __nv_bfloat162 vhi = __halves2bfloat162(xh, yh);
        __nv_bfloat162 vlo = __halves2bfloat162(xl, yl);
        unsigned uhi = *reinterpret_cast<unsigned*>(&vhi);
        unsigned ulo = *reinterpret_cast<unsigned*>(&vlo);
        __stcg(reinterpret_cast<unsigned*>(g_hs + pb * 2048 + j2),        uhi);
        __stcg(reinterpret_cast<unsigned*>(g_hs + pb * 2048 + 1024 + j2), ulo);
        if (xsplit) {
            bf16* xr = xsplit + ((size_t)t * BATCH + pb) * 2048;
            *reinterpret_cast<unsigned*>(xr + j2)        = uhi;
            *reinterpret_cast<unsigned*>(xr + 1024 + j2) = ulo;
        }
        grid_barrier();
    }

    *reinterpret_cast<float2*>(dh + pb * HS + j2) = h2;
    *reinterpret_cast<float2*>(dc + pb * HS + j2) = c2;
}

// =================================================================================
extern "C" void kernel_launch(void* const* d_in, const int* in_sizes, int n_in,
                              void* d_out, int out_size)
{
    const float* x   = (const float*)d_in[0];
    const float* U0  = (const float*)d_in[1];
    const float* V0  = (const float*)d_in[2];
    const float* bi0 = (const float*)d_in[3];
    const float* bh0 = (const float*)d_in[4];
    const float* U1  = (const float*)d_in[5];
    const float* V1  = (const float*)d_in[6];
    const float* bi1 = (const float*)d_in[7];
    const float* bh1 = (const float*)d_in[8];
    float* out = (float*)d_out;

    cudaFuncSetAttribute(k_inproj_t, cudaFuncAttributeMaxDynamicSharedMemorySize, SMEM_INPROJ);
    cudaFuncSetAttribute(k_layer_t,  cudaFuncAttributeMaxDynamicSharedMemorySize, SMEM_LAYER);

    float *pre = nullptr;
    bf16 *xs = nullptr, *us0 = nullptr, *vs0 = nullptr, *us1 = nullptr, *vs1 = nullptr;
    cudaGetSymbolAddress((void**)&pre, g_pre);
    cudaGetSymbolAddress((void**)&xs,  g_xs);
    cudaGetSymbolAddress((void**)&us0, g_Us0);
    cudaGetSymbolAddress((void**)&vs0, g_Vs0);
    cudaGetSymbolAddress((void**)&us1, g_Us1);
    cudaGetSymbolAddress((void**)&vs1, g_Vs1);

    const size_t O_OUT = (size_t)SEQ * BATCH * HS;
    const size_t BH    = (size_t)BATCH * HS;

    k_split_x<<<(MROWS * HS) / 256, 256>>>(x);
    k_split_w<<<(NG * HS) / 256, 256>>>(U0, us0);
    k_split_w<<<(NG * HS) / 256, 256>>>(V0, vs0);
    k_split_w<<<(NG * HS) / 256, 256>>>(U1, us1);
    k_split_w<<<(NG * HS) / 256, 256>>>(V1, vs1);

    const dim3 gIn(NG / 128, MROWS / 128);   // (32, 256)

    // layer 0 (h splits feed layer-1 inproj via g_xs)
    k_inproj_t<<<gIn, 256, SMEM_INPROJ>>>(xs, us0, bi0, bh0, pre);
    k_layer_t<<<NB_PERS, 256, SMEM_LAYER>>>(vs0, pre, nullptr, xs,
                                            out + O_OUT,            // h_f[0]
                                            out + O_OUT + 2 * BH);  // c_f[0]

    // layer 1
    k_inproj_t<<<gIn, 256, SMEM_INPROJ>>>(xs, us1, bi1, bh1, pre);
    k_layer_t<<<NB_PERS, 256, SMEM_LAYER>>>(vs1, pre, out, nullptr,
                                            out + O_OUT + BH,       // h_f[1]
                                            out + O_OUT + 3 * BH);  // c_f[1]
}

// round 5
// speedup vs baseline: 2.0244x; 1.2479x over previous
#include <cuda_runtime.h>
#include <cuda_bf16.h>
#include <cstdint>
#include <cstddef>

#define SEQ   512
#define BATCH 64
#define HS    1024
#define NG    4096
#define MROWS (SEQ*BATCH)     // 32768
#define NB_PERS 128
#define UNITS 8               // hidden units per CTA
#define GP 36                 // padded gate-smem row stride (floats)
#define HB (BATCH*2*HS)       // one h buffer (hi|lo), elements
#define SMEM_LAYER (1024 + 131072 + 32768 + 9216 + 256)
#define SMEM_INPROJ (64*1024 + 1024)

typedef unsigned long long u64;
typedef __nv_bfloat16 bf16;

// ---------------- static device scratch ----------------
__device__ float g_pre[(size_t)MROWS * NG];          // gate pre-activations (permuted cols)
__device__ bf16  g_xs[(size_t)MROWS * 2 * HS];       // input splits (hi|lo); layer0 h splits
__device__ bf16  g_hs[2 * HB];                       // double-buffered h splits
__device__ bf16  g_Us0[(size_t)NG * 2 * HS];         // permuted weight splits
__device__ bf16  g_Vs0[(size_t)NG * 2 * HS];
__device__ bf16  g_Us1[(size_t)NG * 2 * HS];
__device__ bf16  g_Vs1[(size_t)NG * 2 * HS];

// ---------------- grid barrier (release/acquire, monotonic gen) ----------------
__device__ unsigned g_cnt = 0;
__device__ unsigned g_gen = 0;

__device__ __forceinline__ void grid_barrier(unsigned& mygen) {
    __syncthreads();
    if (threadIdx.x == 0) {
        unsigned old;
        asm volatile("atom.add.acq_rel.gpu.u32 %0, [%1], 1;"
                     : "=r"(old) : "l"(&g_cnt) : "memory");
        if (old == (unsigned)(NB_PERS - 1)) {
            asm volatile("st.relaxed.gpu.u32 [%0], 0;" :: "l"(&g_cnt) : "memory");
            asm volatile("red.release.gpu.add.u32 [%0], 1;" :: "l"(&g_gen) : "memory");
        } else {
            unsigned cur;
            do {
                __nanosleep(20);
                asm volatile("ld.acquire.gpu.u32 %0, [%1];"
                             : "=r"(cur) : "l"(&g_gen) : "memory");
            } while (cur == mygen);
        }
    }
    mygen += 1;
    __syncthreads();
}

// ---------------- mma.sync building blocks (validated in R4) ----------------
__device__ __forceinline__ uint32_t smem_u32(const void* p) {
    uint32_t a;
    asm("{ .reg .u64 t; cvta.to.shared.u64 t, %1; cvt.u32.u64 %0, t; }" : "=r"(a) : "l"(p));
    return a;
}
__device__ __forceinline__ void ldsm4(uint32_t* f, uint32_t addr) {
    asm volatile("ldmatrix.sync.aligned.m8n8.x4.shared.b16 {%0,%1,%2,%3}, [%4];"
        : "=r"(f[0]), "=r"(f[1]), "=r"(f[2]), "=r"(f[3]) : "r"(addr));
}
__device__ __forceinline__ void mma16816(float* d, const uint32_t* a, uint32_t b0, uint32_t b1) {
    asm volatile("mma.sync.aligned.m16n8k16.row.col.f32.bf16.bf16.f32 "
        "{%0,%1,%2,%3}, {%4,%5,%6,%7}, {%8,%9}, {%0,%1,%2,%3};"
        : "+f"(d[0]), "+f"(d[1]), "+f"(d[2]), "+f"(d[3])
        : "r"(a[0]), "r"(a[1]), "r"(a[2]), "r"(a[3]), "r"(b0), "r"(b1));
}
__device__ __forceinline__ uint32_t swz(uint32_t r, uint32_t c16) {
    return r * 128u + ((c16 ^ (r & 7u)) << 4);
}
__device__ __forceinline__ uint32_t a_addr(uint32_t base, int lane, int m0, int k0) {
    int sel = lane >> 3;
    uint32_t row = (uint32_t)(m0 + (lane & 7) + ((sel & 1) << 3));
    uint32_t c16 = (uint32_t)((k0 >> 3) + (sel >> 1));
    return base + swz(row, c16);
}
__device__ __forceinline__ uint32_t b_addr(uint32_t base, int lane, int n0, int k0) {
    int sel = lane >> 3;
    uint32_t row = (uint32_t)(n0 + (lane & 7) + ((sel >> 1) << 3));
    uint32_t c16 = (uint32_t)((k0 >> 3) + (sel & 1));
    return base + swz(row, c16);
}
__device__ __forceinline__ void cp16(uint32_t dst, const void* src) {
    asm volatile("cp.async.cg.shared.global [%0], [%1], 16;" :: "r"(dst), "l"(src));
}

// load a [rows x 64] bf16 tile (row stride ld elems) into swizzled smem tile
__device__ __forceinline__ void load_tile(uint32_t sdst, const bf16* __restrict__ src,
                                          int rows, int ld) {
    const int chunks = rows * 8;
    for (int i = threadIdx.x; i < chunks; i += 256) {
        int r = i >> 3, c = i & 7;
        const uint4* p = reinterpret_cast<const uint4*>(src + (size_t)r * ld + c * 8);
        uint4 v = __ldg(p);
        asm volatile("st.shared.v4.b32 [%0], {%1,%2,%3,%4};"
                     :: "r"(sdst + swz((uint32_t)r, (uint32_t)c)),
                        "r"(v.x), "r"(v.y), "r"(v.z), "r"(v.w));
    }
}

// ---------------- activations ----------------
__device__ __forceinline__ float sigmoid_acc(float x) {
    return 1.0f / (1.0f + __expf(-x));
}
__device__ __forceinline__ float tanh_acc(float x) {
    float e = __expf(-2.0f * fabsf(x));
    float t = (1.0f - e) / (1.0f + e);
    return copysignf(t, x);
}
__device__ __forceinline__ void split2(float v, bf16& hi, bf16& lo) {
    hi = __float2bfloat16(v);
    lo = __float2bfloat16(v - __bfloat162float(hi));
}

// =================================================================================
// split kernels. Weight rows are gate-permuted: orig row r = g*1024+u -> 4u+g.
// =================================================================================
__global__ __launch_bounds__(256) void k_split_x(const float* __restrict__ x) {
    size_t i = (size_t)blockIdx.x * 256 + threadIdx.x;
    size_t m = i >> 10, k = i & 1023;
    bf16 hi, lo; split2(x[i], hi, lo);
    g_xs[m * 2048 + k]        = hi;
    g_xs[m * 2048 + 1024 + k] = lo;
}
__global__ __launch_bounds__(256) void k_split_w(const float* __restrict__ W, bf16* __restrict__ dst) {
    size_t i = (size_t)blockIdx.x * 256 + threadIdx.x;
    size_t n = i >> 10, k = i & 1023;
    size_t gidx = n >> 10, u = n & 1023;
    size_t np = u * 4 + gidx;                 // permuted row
    bf16 hi, lo; split2(W[i], hi, lo);
    dst[np * 2048 + k]        = hi;
    dst[np * 2048 + 1024 + k] = lo;
}

// =================================================================================
// Input projection (HMMA, validated R4): pre[128m,128n] = [xhi|xlo] @ [Whi|Wlo]^T
// (bias now added in the layer pointwise)
// =================================================================================
__global__ __launch_bounds__(256, 2) void k_inproj_t(
    const bf16* __restrict__ A, const bf16* __restrict__ W,
    float* __restrict__ C)
{
    extern __shared__ char dsm[];
    const uint32_t sbase = (smem_u32(dsm) + 1023u) & ~1023u;
    const uint32_t sAh = sbase, sAl = sbase + 16384, sBh = sbase + 32768, sBl = sbase + 49152;
    const int tid = threadIdx.x, wid = tid >> 5, lane = tid & 31;
    const int m0 = blockIdx.y * 128, n0 = blockIdx.x * 128;
    const int mi = wid & 3, ni = wid >> 2;

    float acc[2][8][4];
#pragma unroll
    for (int a = 0; a < 2; a++)
#pragma unroll
        for (int b = 0; b < 8; b++)
#pragma unroll
            for (int cpos = 0; cpos < 4; cpos++) acc[a][b][cpos] = 0.f;

    const bf16* Arow = A + (size_t)m0 * 2048;
    const bf16* Wrow = W + (size_t)n0 * 2048;

    for (int kb = 0; kb < 16; kb++) {
        const int k0g = kb * 64;
        load_tile(sAh, Arow + k0g,        128, 2048);
        load_tile(sAl, Arow + 1024 + k0g, 128, 2048);
        load_tile(sBh, Wrow + k0g,        128, 2048);
        load_tile(sBl, Wrow + 1024 + k0g, 128, 2048);
        __syncthreads();

#pragma unroll
        for (int ks = 0; ks < 4; ks++) {
            const int k0 = ks * 16;
            uint32_t ah[2][4], al[2][4];
#pragma unroll
            for (int mf = 0; mf < 2; mf++) {
                ldsm4(ah[mf], a_addr(sAh, lane, mi * 32 + mf * 16, k0));
                ldsm4(al[mf], a_addr(sAl, lane, mi * 32 + mf * 16, k0));
            }
#pragma unroll
            for (int np = 0; np < 4; np++) {
                const int nt = ni * 64 + np * 16;
                uint32_t bh[4], bl[4];
                ldsm4(bh, b_addr(sBh, lane, nt, k0));
#pragma unroll
                for (int mf = 0; mf < 2; mf++) {
                    mma16816(acc[mf][np * 2],     ah[mf], bh[0], bh[1]);
                    mma16816(acc[mf][np * 2 + 1], ah[mf], bh[2], bh[3]);
                    mma16816(acc[mf][np * 2],     al[mf], bh[0], bh[1]);
                    mma16816(acc[mf][np * 2 + 1], al[mf], bh[2], bh[3]);
                }
                ldsm4(bl, b_addr(sBl, lane, nt, k0));
#pragma unroll
                for (int mf = 0; mf < 2; mf++) {
                    mma16816(acc[mf][np * 2],     ah[mf], bl[0], bl[1]);
                    mma16816(acc[mf][np * 2 + 1], ah[mf], bl[2], bl[3]);
                }
            }
        }
        __syncthreads();
    }

    const int r = lane >> 2, cq = (lane & 3) * 2;
#pragma unroll
    for (int mf = 0; mf < 2; mf++) {
#pragma unroll
        for (int nf = 0; nf < 8; nf++) {
            const int ncol = n0 + ni * 64 + nf * 8 + cq;
            const int row0 = m0 + mi * 32 + mf * 16 + r;
            *reinterpret_cast<float2*>(C + (size_t)row0 * NG + ncol) =
                make_float2(acc[mf][nf][0], acc[mf][nf][1]);
            *reinterpret_cast<float2*>(C + (size_t)(row0 + 8) * NG + ncol) =
                make_float2(acc[mf][nf][2], acc[mf][nf][3]);
        }
    }
}

// =================================================================================
// Persistent LSTM layer: 128 CTAs, CTA bx owns gate cols [32bx,32bx+32) = units
// [8bx, 8bx+8). Full K=1024, V slice smem-resident, ONE grid barrier per step.
// smem: V 2x16 tiles [32x64] = 128KB | A 2buf x 2split [64x64] = 32KB | gates 9KB.
// =================================================================================
__global__ __launch_bounds__(256) void k_layer_t(
    const bf16* __restrict__ Vs, const float* __restrict__ pre,
    const float* __restrict__ b1, const float* __restrict__ b2,
    float* __restrict__ outbuf, bf16* __restrict__ xsplit,
    float* __restrict__ dh, float* __restrict__ dc)
{
    extern __shared__ char dsm[];
    const uint32_t sbase = (smem_u32(dsm) + 1023u) & ~1023u;
    const uint32_t sV = sbase;                  // (s*16+kb)*4096
    const uint32_t sA = sbase + 131072;         // buf*16384 + s*8192
    const uint32_t sG = sbase + 131072 + 32768; // 64*GP floats
    const int tid = threadIdx.x, wid = tid >> 5, lane = tid & 31;
    const int bx = blockIdx.x;
    const int mi = wid & 3, ni = wid >> 2;
    const int b  = tid >> 2;            // batch 0..63
    const int ul = (tid & 3) * 2;       // local unit 0,2,4,6
    const int u0g = bx * UNITS + ul;    // global unit (even)
    const int col0 = bx * 32 + 4 * ul;  // global gate col of unit ul

    // V slice resident (hi split tiles 0..15, lo split 16..31)
    for (int s = 0; s < 2; s++)
        for (int kb = 0; kb < 16; kb++)
            load_tile(sV + (uint32_t)(s * 16 + kb) * 4096u,
                      Vs + (size_t)(bx * 32) * 2048 + s * 1024 + kb * 64,
                      32, 2048);

    // bias (permuted col -> orig row)
    float bias[8];
#pragma unroll
    for (int j = 0; j < 8; j++) {
        int n = col0 + j;
        int orig = ((n & 3) << 10) + (n >> 2);
        bias[j] = __ldg(b1 + orig) + __ldg(b2 + orig);
    }

    unsigned mygen;
    asm volatile("ld.relaxed.gpu.u32 %0, [%1];" : "=r"(mygen) : "l"(&g_gen));

    float2 c2 = make_float2(0.f, 0.f), h2 = make_float2(0.f, 0.f);
    // zero initial read buffer (buf 1)
    __stcg(reinterpret_cast<unsigned*>(g_hs + (size_t)HB + b * 2048 + u0g), 0u);
    __stcg(reinterpret_cast<unsigned*>(g_hs + (size_t)HB + b * 2048 + 1024 + u0g), 0u);
    grid_barrier(mygen);

    for (int t = 0; t < SEQ; t++) {
        const bf16* hsrc = g_hs + (size_t)((t + 1) & 1) * HB;

        // prefetch this thread's pre slice (hidden under the GEMM)
        const float* prow = pre + ((size_t)t * BATCH + b) * NG + col0;
        float4 p0 = __ldg(reinterpret_cast<const float4*>(prow));
        float4 p1 = __ldg(reinterpret_cast<const float4*>(prow + 4));

        // prologue: A k-block 0 -> buf 0
#pragma unroll
        for (int s = 0; s < 2; s++) {
            uint32_t td = sA + (uint32_t)s * 8192u;
            const bf16* src = hsrc + s * 1024;
#pragma unroll
            for (int q = 0; q < 2; q++) {
                int i = tid + q * 256;
                int r = i >> 3, c = i & 7;
                cp16(td + swz(r, c), src + (size_t)r * 2048 + c * 8);
            }
        }
        asm volatile("cp.async.commit_group;");

        float acc[2][4];
#pragma unroll
        for (int f = 0; f < 2; f++)
#pragma unroll
            for (int j = 0; j < 4; j++) acc[f][j] = 0.f;

#pragma unroll 1
        for (int kb = 0; kb < 16; kb++) {
            asm volatile("cp.async.wait_group 0;");
            __syncthreads();
            if (kb < 15) {  // stream next k-block into other buffer (overlaps MMA)
                uint32_t bufn = (uint32_t)((kb + 1) & 1) * 16384u;
#pragma unroll
                for (int s = 0; s < 2; s++) {
                    uint32_t td = sA + bufn + (uint32_t)s * 8192u;
                    const bf16* src = hsrc + s * 1024 + (kb + 1) * 64;
#pragma unroll
                    for (int q = 0; q < 2; q++) {
                        int i = tid + q * 256;
                        int r = i >> 3, c = i & 7;
                        cp16(td + swz(r, c), src + (size_t)r * 2048 + c * 8);
                    }
                }
                asm volatile("cp.async.commit_group;");
            }
            const uint32_t ahB = sA + (uint32_t)(kb & 1) * 16384u;
            const uint32_t alB = ahB + 8192u;
            const uint32_t vhB = sV + (uint32_t)kb * 4096u;
            const uint32_t vlB = sV + (uint32_t)(16 + kb) * 4096u;
#pragma unroll
            for (int kst = 0; kst < 4; kst++) {
                const int k0 = kst * 16;
                uint32_t ah[4], al[4], bh[4], bl[4];
                ldsm4(ah, a_addr(ahB, lane, mi * 16, k0));
                ldsm4(bh, b_addr(vhB, lane, ni * 16, k0));
                ldsm4(al, a_addr(alB, lane, mi * 16, k0));
                ldsm4(bl, b_addr(vlB, lane, ni * 16, k0));
                mma16816(acc[0], ah, bh[0], bh[1]);
                mma16816(acc[1], ah, bh[2], bh[3]);
                mma16816(acc[0], al, bh[0], bh[1]);
                mma16816(acc[1], al, bh[2], bh[3]);
                mma16816(acc[0], ah, bl[0], bl[1]);
                mma16816(acc[1], ah, bl[2], bl[3]);
            }
        }

        // epilogue: acc frags -> gate smem
        {
            const int r = lane >> 2, cq = (lane & 3) * 2;
            const int row = mi * 16 + r;
#pragma unroll
            for (int f = 0; f < 2; f++) {
                const int col = ni * 16 + f * 8 + cq;
                asm volatile("st.shared.v2.f32 [%0], {%1,%2};"
                    :: "r"(sG + (uint32_t)(row * GP + col) * 4u), "f"(acc[f][0]), "f"(acc[f][1]));
                asm volatile("st.shared.v2.f32 [%0], {%1,%2};"
                    :: "r"(sG + (uint32_t)((row + 8) * GP + col) * 4u), "f"(acc[f][2]), "f"(acc[f][3]));
            }
        }
        __syncthreads();

        // pointwise: 2 units per thread
        float4 ga, gb;
        asm volatile("ld.shared.v4.f32 {%0,%1,%2,%3}, [%4];"
            : "=f"(ga.x), "=f"(ga.y), "=f"(ga.z), "=f"(ga.w)
            : "r"(sG + (uint32_t)(b * GP + 4 * ul) * 4u));
        asm volatile("ld.shared.v4.f32 {%0,%1,%2,%3}, [%4];"
            : "=f"(gb.x), "=f"(gb.y), "=f"(gb.z), "=f"(gb.w)
            : "r"(sG + (uint32_t)(b * GP + 4 * ul + 4) * 4u));
        {
            float iv = sigmoid_acc(ga.x + p0.x + bias[0]);
            float fv = sigmoid_acc(ga.y + p0.y + bias[1]);
            float gv = tanh_acc   (ga.z + p0.z + bias[2]);
            float ov = sigmoid_acc(ga.w + p0.w + bias[3]);
            c2.x = fv * c2.x + iv * gv;
            h2.x = ov * tanh_acc(c2.x);
        }
        {
            float iv = sigmoid_acc(gb.x + p1.x + bias[4]);
            float fv = sigmoid_acc(gb.y + p1.y + bias[5]);
            float gv = tanh_acc   (gb.z + p1.z + bias[6]);
            float ov = sigmoid_acc(gb.w + p1.w + bias[7]);
            c2.y = fv * c2.y + iv * gv;
            h2.y = ov * tanh_acc(c2.y);
        }

        // publish h splits (write buffer t&1)
        bf16 xh, xl, yh, yl;
        split2(h2.x, xh, xl);
        split2(h2.y, yh, yl);
        __nv_bfloat162 vhi = __halves2bfloat162(xh, yh);
        __nv_bfloat162 vlo = __halves2bfloat162(xl, yl);
        unsigned uhi = *reinterpret_cast<unsigned*>(&vhi);
        unsigned ulo = *reinterpret_cast<unsigned*>(&vlo);
        bf16* wdst = g_hs + (size_t)(t & 1) * HB + b * 2048;
        __stcg(reinterpret_cast<unsigned*>(wdst + u0g), uhi);
        __stcg(reinterpret_cast<unsigned*>(wdst + 1024 + u0g), ulo);
        if (outbuf)
            *reinterpret_cast<float2*>(outbuf + ((size_t)t * BATCH + b) * HS + u0g) = h2;
        if (xsplit) {
            bf16* xr = xsplit + ((size_t)t * BATCH + b) * 2048;
            *reinterpret_cast<unsigned*>(xr + u0g) = uhi;
            *reinterpret_cast<unsigned*>(xr + 1024 + u0g) = ulo;
        }
        grid_barrier(mygen);
    }

    *reinterpret_cast<float2*>(dh + b * HS + u0g) = h2;
    *reinterpret_cast<float2*>(dc + b * HS + u0g) = c2;
}

// =================================================================================
extern "C" void kernel_launch(void* const* d_in, const int* in_sizes, int n_in,
                              void* d_out, int out_size)
{
    const float* x   = (const float*)d_in[0];
    const float* U0  = (const float*)d_in[1];
    const float* V0  = (const float*)d_in[2];
    const float* bi0 = (const float*)d_in[3];
    const float* bh0 = (const float*)d_in[4];
    const float* U1  = (const float*)d_in[5];
    const float* V1  = (const float*)d_in[6];
    const float* bi1 = (const float*)d_in[7];
    const float* bh1 = (const float*)d_in[8];
    float* out = (float*)d_out;

    cudaFuncSetAttribute(k_inproj_t, cudaFuncAttributeMaxDynamicSharedMemorySize, SMEM_INPROJ);
    cudaFuncSetAttribute(k_layer_t,  cudaFuncAttributeMaxDynamicSharedMemorySize, SMEM_LAYER);

    float *pre = nullptr;
    bf16 *xs = nullptr, *us0 = nullptr, *vs0 = nullptr, *us1 = nullptr, *vs1 = nullptr;
    cudaGetSymbolAddress((void**)&pre, g_pre);
    cudaGetSymbolAddress((void**)&xs,  g_xs);
    cudaGetSymbolAddress((void**)&us0, g_Us0);
    cudaGetSymbolAddress((void**)&vs0, g_Vs0);
    cudaGetSymbolAddress((void**)&us1, g_Us1);
    cudaGetSymbolAddress((void**)&vs1, g_Vs1);

    const size_t O_OUT = (size_t)SEQ * BATCH * HS;
    const size_t BH    = (size_t)BATCH * HS;

    k_split_x<<<(MROWS * HS) / 256, 256>>>(x);
    k_split_w<<<(NG * HS) / 256, 256>>>(U0, us0);
    k_split_w<<<(NG * HS) / 256, 256>>>(V0, vs0);
    k_split_w<<<(NG * HS) / 256, 256>>>(U1, us1);
    k_split_w<<<(NG * HS) / 256, 256>>>(V1, vs1);

    const dim3 gIn(NG / 128, MROWS / 128);   // (32, 256)

    // layer 0 (h splits feed layer-1 inproj via g_xs)
    k_inproj_t<<<gIn, 256, SMEM_INPROJ>>>(xs, us0, pre);
    k_layer_t<<<NB_PERS, 256, SMEM_LAYER>>>(vs0, pre, bi0, bh0, nullptr, xs,
                                            out + O_OUT,            // h_f[0]
                                            out + O_OUT + 2 * BH);  // c_f[0]

    // layer 1
    k_inproj_t<<<gIn, 256, SMEM_INPROJ>>>(xs, us1, pre);
    k_layer_t<<<NB_PERS, 256, SMEM_LAYER>>>(vs1, pre, bi1, bh1, out, nullptr,
                                            out + O_OUT + BH,       // h_f[1]
                                            out + O_OUT + 3 * BH);  // c_f[1]
}

// round 6
// speedup vs baseline: 2.4071x; 1.1890x over previous
#include <cuda_runtime.h>
#include <cuda_bf16.h>
#include <cstdint>
#include <cstddef>

#define SEQ   512
#define BATCH 64
#define HS    1024
#define NG    4096
#define MROWS (SEQ*BATCH)     // 32768
#define NB_PERS 128
#define UNITS 8               // hidden units per CTA
#define GP 36                 // padded gate-smem row stride (floats)
#define HB (BATCH*2*HS)       // one h buffer (hi|lo), elements
#define SMEM_LAYER (1024 + 131072 + 32768 + 9216 + 256)
#define SMEM_INPROJ (131072 + 1024)

typedef unsigned long long u64;
typedef __nv_bfloat16 bf16;

// ---------------- static device scratch ----------------
__device__ float g_pre[(size_t)MROWS * NG];          // gate pre-activations (permuted cols)
__device__ bf16  g_xs[(size_t)MROWS * 2 * HS];       // input splits (hi|lo); layer0 h splits
__device__ bf16  g_hs[2 * HB];                       // double-buffered h splits
__device__ bf16  g_Us0[(size_t)NG * 2 * HS];         // permuted weight splits
__device__ bf16  g_Vs0[(size_t)NG * 2 * HS];
__device__ bf16  g_Us1[(size_t)NG * 2 * HS];
__device__ bf16  g_Vs1[(size_t)NG * 2 * HS];

// ---------------- grid barrier (release/acquire, monotonic gen) ----------------
__device__ unsigned g_cnt = 0;
__device__ unsigned g_gen = 0;

__device__ __forceinline__ void grid_barrier(unsigned& mygen) {
    __syncthreads();
    if (threadIdx.x == 0) {
        unsigned old;
        asm volatile("atom.add.acq_rel.gpu.u32 %0, [%1], 1;"
                     : "=r"(old) : "l"(&g_cnt) : "memory");
        if (old == (unsigned)(NB_PERS - 1)) {
            asm volatile("st.relaxed.gpu.u32 [%0], 0;" :: "l"(&g_cnt) : "memory");
            asm volatile("red.release.gpu.add.u32 [%0], 1;" :: "l"(&g_gen) : "memory");
        } else {
            unsigned cur;
            do {
                __nanosleep(20);
                asm volatile("ld.acquire.gpu.u32 %0, [%1];"
                             : "=r"(cur) : "l"(&g_gen) : "memory");
            } while (cur == mygen);
        }
    }
    mygen += 1;
    __syncthreads();
}

// ---------------- mma.sync building blocks (validated R4/R5) ----------------
__device__ __forceinline__ uint32_t smem_u32(const void* p) {
    uint32_t a;
    asm("{ .reg .u64 t; cvta.to.shared.u64 t, %1; cvt.u32.u64 %0, t; }" : "=r"(a) : "l"(p));
    return a;
}
__device__ __forceinline__ void ldsm4(uint32_t* f, uint32_t addr) {
    asm volatile("ldmatrix.sync.aligned.m8n8.x4.shared.b16 {%0,%1,%2,%3}, [%4];"
        : "=r"(f[0]), "=r"(f[1]), "=r"(f[2]), "=r"(f[3]) : "r"(addr));
}
__device__ __forceinline__ void mma16816(float* d, const uint32_t* a, uint32_t b0, uint32_t b1) {
    asm volatile("mma.sync.aligned.m16n8k16.row.col.f32.bf16.bf16.f32 "
        "{%0,%1,%2,%3}, {%4,%5,%6,%7}, {%8,%9}, {%0,%1,%2,%3};"
        : "+f"(d[0]), "+f"(d[1]), "+f"(d[2]), "+f"(d[3])
        : "r"(a[0]), "r"(a[1]), "r"(a[2]), "r"(a[3]), "r"(b0), "r"(b1));
}
__device__ __forceinline__ uint32_t swz(uint32_t r, uint32_t c16) {
    return r * 128u + ((c16 ^ (r & 7u)) << 4);
}
__device__ __forceinline__ uint32_t a_addr(uint32_t base, int lane, int m0, int k0) {
    int sel = lane >> 3;
    uint32_t row = (uint32_t)(m0 + (lane & 7) + ((sel & 1) << 3));
    uint32_t c16 = (uint32_t)((k0 >> 3) + (sel >> 1));
    return base + swz(row, c16);
}
__device__ __forceinline__ uint32_t b_addr(uint32_t base, int lane, int n0, int k0) {
    int sel = lane >> 3;
    uint32_t row = (uint32_t)(n0 + (lane & 7) + ((sel >> 1) << 3));
    uint32_t c16 = (uint32_t)((k0 >> 3) + (sel & 1));
    return base + swz(row, c16);
}
__device__ __forceinline__ void cp16(uint32_t dst, const void* src) {
    asm volatile("cp.async.cg.shared.global [%0], [%1], 16;" :: "r"(dst), "l"(src));
}

// load a [rows x 64] bf16 tile (row stride ld elems) into swizzled smem (sync path)
__device__ __forceinline__ void load_tile(uint32_t sdst, const bf16* __restrict__ src,
                                          int rows, int ld) {
    const int chunks = rows * 8;
    for (int i = threadIdx.x; i < chunks; i += 256) {
        int r = i >> 3, c = i & 7;
        const uint4* p = reinterpret_cast<const uint4*>(src + (size_t)r * ld + c * 8);
        uint4 v = __ldg(p);
        asm volatile("st.shared.v4.b32 [%0], {%1,%2,%3,%4};"
                     :: "r"(sdst + swz((uint32_t)r, (uint32_t)c)),
                        "r"(v.x), "r"(v.y), "r"(v.z), "r"(v.w));
    }
}
// async stage of a [128 x 64] tile (row stride 2048) via cp.async
__device__ __forceinline__ void stage_tile_cp(uint32_t sdst, const bf16* __restrict__ src) {
    const int tid = threadIdx.x;
#pragma unroll
    for (int q = 0; q < 4; q++) {
        int i = tid + q * 256;               // 0..1023
        int r = i >> 3, c = i & 7;
        cp16(sdst + swz((uint32_t)r, (uint32_t)c), src + (size_t)r * 2048 + c * 8);
    }
}

// ---------------- activations ----------------
__device__ __forceinline__ float sigmoid_acc(float x) {
    return 1.0f / (1.0f + __expf(-x));
}
__device__ __forceinline__ float tanh_acc(float x) {
    float e = __expf(-2.0f * fabsf(x));
    float t = (1.0f - e) / (1.0f + e);
    return copysignf(t, x);
}
__device__ __forceinline__ void split2(float v, bf16& hi, bf16& lo) {
    hi = __float2bfloat16(v);
    lo = __float2bfloat16(v - __bfloat162float(hi));
}

// =================================================================================
// split kernels. Weight rows gate-permuted: orig row r = g*1024+u -> 4u+g.
// All four weight matrices in ONE launch (also fixes ncu -s 5 capture target).
// =================================================================================
__global__ __launch_bounds__(256) void k_split_x(const float* __restrict__ x) {
    size_t i = (size_t)blockIdx.x * 256 + threadIdx.x;
    size_t m = i >> 10, k = i & 1023;
    bf16 hi, lo; split2(x[i], hi, lo);
    g_xs[m * 2048 + k]        = hi;
    g_xs[m * 2048 + 1024 + k] = lo;
}
__global__ __launch_bounds__(256) void k_split_w4(
    const float* __restrict__ W0, const float* __restrict__ W1,
    const float* __restrict__ W2, const float* __restrict__ W3,
    bf16* __restrict__ d0, bf16* __restrict__ d1,
    bf16* __restrict__ d2, bf16* __restrict__ d3)
{
    const float* W; bf16* dst;
    switch (blockIdx.y) {
        case 0:  W = W0; dst = d0; break;
        case 1:  W = W1; dst = d1; break;
        case 2:  W = W2; dst = d2; break;
        default: W = W3; dst = d3; break;
    }
    size_t i = (size_t)blockIdx.x * 256 + threadIdx.x;
    size_t n = i >> 10, k = i & 1023;
    size_t gidx = n >> 10, u = n & 1023;
    size_t np = u * 4 + gidx;
    bf16 hi, lo; split2(W[i], hi, lo);
    dst[np * 2048 + k]        = hi;
    dst[np * 2048 + 1024 + k] = lo;
}

// =================================================================================
// Input projection, cp.async double-buffered: pre[128m,128n] += [xhi|xlo]@[Whi|Wlo]^T
// Stage = {Ah, Al, Bh, Bl} 128x64 tiles (64KB); 2 stages; K-chunk 64; 16 chunks.
// =================================================================================
__global__ __launch_bounds__(256) void k_inproj_t(
    const bf16* __restrict__ A, const bf16* __restrict__ W,
    float* __restrict__ C)
{
    extern __shared__ char dsm[];
    const uint32_t sbase = (smem_u32(dsm) + 1023u) & ~1023u;
    const int tid = threadIdx.x, wid = tid >> 5, lane = tid & 31;
    const int m0 = blockIdx.y * 128, n0 = blockIdx.x * 128;
    const int mi = wid & 3, ni = wid >> 2;

    const bf16* Arow = A + (size_t)m0 * 2048;
    const bf16* Wrow = W + (size_t)n0 * 2048;

    auto issue_stage = [&](int kb) {
        const uint32_t st = sbase + (uint32_t)(kb & 1) * 65536u;
        const int k0g = kb * 64;
        stage_tile_cp(st,          Arow + k0g);
        stage_tile_cp(st + 16384u, Arow + 1024 + k0g);
        stage_tile_cp(st + 32768u, Wrow + k0g);
        stage_tile_cp(st + 49152u, Wrow + 1024 + k0g);
        asm volatile("cp.async.commit_group;");
    };

    float acc[2][8][4];
#pragma unroll
    for (int a = 0; a < 2; a++)
#pragma unroll
        for (int b = 0; b < 8; b++)
#pragma unroll
            for (int cpos = 0; cpos < 4; cpos++) acc[a][b][cpos] = 0.f;

    issue_stage(0);

#pragma unroll 1
    for (int kb = 0; kb < 16; kb++) {
        asm volatile("cp.async.wait_group 0;");
        __syncthreads();
        if (kb < 15) issue_stage(kb + 1);

        const uint32_t st = sbase + (uint32_t)(kb & 1) * 65536u;
        const uint32_t sAh = st, sAl = st + 16384u, sBh = st + 32768u, sBl = st + 49152u;
#pragma unroll
        for (int ks = 0; ks < 4; ks++) {
            const int k0 = ks * 16;
            uint32_t ah[2][4], al[2][4];
#pragma unroll
            for (int mf = 0; mf < 2; mf++) {
                ldsm4(ah[mf], a_addr(sAh, lane, mi * 32 + mf * 16, k0));
                ldsm4(al[mf], a_addr(sAl, lane, mi * 32 + mf * 16, k0));
            }
#pragma unroll
            for (int np = 0; np < 4; np++) {
                const int nt = ni * 64 + np * 16;
                uint32_t bh[4], bl[4];
                ldsm4(bh, b_addr(sBh, lane, nt, k0));
#pragma unroll
                for (int mf = 0; mf < 2; mf++) {
                    mma16816(acc[mf][np * 2],     ah[mf], bh[0], bh[1]);
                    mma16816(acc[mf][np * 2 + 1], ah[mf], bh[2], bh[3]);
                    mma16816(acc[mf][np * 2],     al[mf], bh[0], bh[1]);
                    mma16816(acc[mf][np * 2 + 1], al[mf], bh[2], bh[3]);
                }
                ldsm4(bl, b_addr(sBl, lane, nt, k0));
#pragma unroll
                for (int mf = 0; mf < 2; mf++) {
                    mma16816(acc[mf][np * 2],     ah[mf], bl[0], bl[1]);
                    mma16816(acc[mf][np * 2 + 1], ah[mf], bl[2], bl[3]);
                }
            }
        }
        __syncthreads();   // all warps done reading stage kb before it is overwritten
    }

    const int r = lane >> 2, cq = (lane & 3) * 2;
#pragma unroll
    for (int mf = 0; mf < 2; mf++) {
#pragma unroll
        for (int nf = 0; nf < 8; nf++) {
            const int ncol = n0 + ni * 64 + nf * 8 + cq;
            const int row0 = m0 + mi * 32 + mf * 16 + r;
            *reinterpret_cast<float2*>(C + (size_t)row0 * NG + ncol) =
                make_float2(acc[mf][nf][0], acc[mf][nf][1]);
            *reinterpret_cast<float2*>(C + (size_t)(row0 + 8) * NG + ncol) =
                make_float2(acc[mf][nf][2], acc[mf][nf][3]);
        }
    }
}

// =================================================================================
// Persistent LSTM layer (unchanged from R5 — passed, near structure floor).
// =================================================================================
__global__ __launch_bounds__(256) void k_layer_t(
    const bf16* __restrict__ Vs, const float* __restrict__ pre,
    const float* __restrict__ b1, const float* __restrict__ b2,
    float* __restrict__ outbuf, bf16* __restrict__ xsplit,
    float* __restrict__ dh, float* __restrict__ dc)
{
    extern __shared__ char dsm[];
    const uint32_t sbase = (smem_u32(dsm) + 1023u) & ~1023u;
    const uint32_t sV = sbase;
    const uint32_t sA = sbase + 131072;
    const uint32_t sG = sbase + 131072 + 32768;
    const int tid = threadIdx.x, wid = tid >> 5, lane = tid & 31;
    const int bx = blockIdx.x;
    const int mi = wid & 3, ni = wid >> 2;
    const int b  = tid >> 2;
    const int ul = (tid & 3) * 2;
    const int u0g = bx * UNITS + ul;
    const int col0 = bx * 32 + 4 * ul;

    for (int s = 0; s < 2; s++)
        for (int kb = 0; kb < 16; kb++)
            load_tile(sV + (uint32_t)(s * 16 + kb) * 4096u,
                      Vs + (size_t)(bx * 32) * 2048 + s * 1024 + kb * 64,
                      32, 2048);

    float bias[8];
#pragma unroll
    for (int j = 0; j < 8; j++) {
        int n = col0 + j;
        int orig = ((n & 3) << 10) + (n >> 2);
        bias[j] = __ldg(b1 + orig) + __ldg(b2 + orig);
    }

    unsigned mygen;
    asm volatile("ld.relaxed.gpu.u32 %0, [%1];" : "=r"(mygen) : "l"(&g_gen));

    float2 c2 = make_float2(0.f, 0.f), h2 = make_float2(0.f, 0.f);
    __stcg(reinterpret_cast<unsigned*>(g_hs + (size_t)HB + b * 2048 + u0g), 0u);
    __stcg(reinterpret_cast<unsigned*>(g_hs + (size_t)HB + b * 2048 + 1024 + u0g), 0u);
    grid_barrier(mygen);

    for (int t = 0; t < SEQ; t++) {
        const bf16* hsrc = g_hs + (size_t)((t + 1) & 1) * HB;

        const float* prow = pre + ((size_t)t * BATCH + b) * NG + col0;
        float4 p0 = __ldg(reinterpret_cast<const float4*>(prow));
        float4 p1 = __ldg(reinterpret_cast<const float4*>(prow + 4));

#pragma unroll
        for (int s = 0; s < 2; s++) {
            uint32_t td = sA + (uint32_t)s * 8192u;
            const bf16* src = hsrc + s * 1024;
#pragma unroll
            for (int q = 0; q < 2; q++) {
                int i = tid + q * 256;
                int r = i >> 3, c = i & 7;
                cp16(td + swz(r, c), src + (size_t)r * 2048 + c * 8);
            }
        }
        asm volatile("cp.async.commit_group;");

        float acc[2][4];
#pragma unroll
        for (int f = 0; f < 2; f++)
#pragma unroll
            for (int j = 0; j < 4; j++) acc[f][j] = 0.f;

#pragma unroll 1
        for (int kb = 0; kb < 16; kb++) {
            asm volatile("cp.async.wait_group 0;");
            __syncthreads();
            if (kb < 15) {
                uint32_t bufn = (uint32_t)((kb + 1) & 1) * 16384u;
#pragma unroll
                for (int s = 0; s < 2; s++) {
                    uint32_t td = sA + bufn + (uint32_t)s * 8192u;
                    const bf16* src = hsrc + s * 1024 + (kb + 1) * 64;
#pragma unroll
                    for (int q = 0; q < 2; q++) {
                        int i = tid + q * 256;
                        int r = i >> 3, c = i & 7;
                        cp16(td + swz(r, c), src + (size_t)r * 2048 + c * 8);
                    }
                }
                asm volatile("cp.async.commit_group;");
            }
            const uint32_t ahB = sA + (uint32_t)(kb & 1) * 16384u;
            const uint32_t alB = ahB + 8192u;
            const uint32_t vhB = sV + (uint32_t)kb * 4096u;
            const uint32_t vlB = sV + (uint32_t)(16 + kb) * 4096u;
#pragma unroll
            for (int kst = 0; kst < 4; kst++) {
                const int k0 = kst * 16;
                uint32_t ah[4], al[4], bh[4], bl[4];
                ldsm4(ah, a_addr(ahB, lane, mi * 16, k0));
                ldsm4(bh, b_addr(vhB, lane, ni * 16, k0));
                ldsm4(al, a_addr(alB, lane, mi * 16, k0));
                ldsm4(bl, b_addr(vlB, lane, ni * 16, k0));
                mma16816(acc[0], ah, bh[0], bh[1]);
                mma16816(acc[1], ah, bh[2], bh[3]);
                mma16816(acc[0], al, bh[0], bh[1]);
                mma16816(acc[1], al, bh[2], bh[3]);
                mma16816(acc[0], ah, bl[0], bl[1]);
                mma16816(acc[1], ah, bl[2], bl[3]);
            }
        }

        {
            const int r = lane >> 2, cq = (lane & 3) * 2;
            const int row = mi * 16 + r;
#pragma unroll
            for (int f = 0; f < 2; f++) {
                const int col = ni * 16 + f * 8 + cq;
                asm volatile("st.shared.v2.f32 [%0], {%1,%2};"
                    :: "r"(sG + (uint32_t)(row * GP + col) * 4u), "f"(acc[f][0]), "f"(acc[f][1]));
                asm volatile("st.shared.v2.f32 [%0], {%1,%2};"
                    :: "r"(sG + (uint32_t)((row + 8) * GP + col) * 4u), "f"(acc[f][2]), "f"(acc[f][3]));
            }
        }
        __syncthreads();

        float4 ga, gb;
        asm volatile("ld.shared.v4.f32 {%0,%1,%2,%3}, [%4];"
            : "=f"(ga.x), "=f"(ga.y), "=f"(ga.z), "=f"(ga.w)
            : "r"(sG + (uint32_t)(b * GP + 4 * ul) * 4u));
        asm volatile("ld.shared.v4.f32 {%0,%1,%2,%3}, [%4];"
            : "=f"(gb.x), "=f"(gb.y), "=f"(gb.z), "=f"(gb.w)
            : "r"(sG + (uint32_t)(b * GP + 4 * ul + 4) * 4u));
        {
            float iv = sigmoid_acc(ga.x + p0.x + bias[0]);
            float fv = sigmoid_acc(ga.y + p0.y + bias[1]);
            float gv = tanh_acc   (ga.z + p0.z + bias[2]);
            float ov = sigmoid_acc(ga.w + p0.w + bias[3]);
            c2.x = fv * c2.x + iv * gv;
            h2.x = ov * tanh_acc(c2.x);
        }
        {
            float iv = sigmoid_acc(gb.x + p1.x + bias[4]);
            float fv = sigmoid_acc(gb.y + p1.y + bias[5]);
            float gv = tanh_acc   (gb.z + p1.z + bias[6]);
            float ov = sigmoid_acc(gb.w + p1.w + bias[7]);
            c2.y = fv * c2.y + iv * gv;
            h2.y = ov * tanh_acc(c2.y);
        }

        bf16 xh, xl, yh, yl;
        split2(h2.x, xh, xl);
        split2(h2.y, yh, yl);
        __nv_bfloat162 vhi = __halves2bfloat162(xh, yh);
        __nv_bfloat162 vlo = __halves2bfloat162(xl, yl);
        unsigned uhi = *reinterpret_cast<unsigned*>(&vhi);
        unsigned ulo = *reinterpret_cast<unsigned*>(&vlo);
        bf16* wdst = g_hs + (size_t)(t & 1) * HB + b * 2048;
        __stcg(reinterpret_cast<unsigned*>(wdst + u0g), uhi);
        __stcg(reinterpret_cast<unsigned*>(wdst + 1024 + u0g), ulo);
        if (outbuf)
            *reinterpret_cast<float2*>(outbuf + ((size_t)t * BATCH + b) * HS + u0g) = h2;
        if (xsplit) {
            bf16* xr = xsplit + ((size_t)t * BATCH + b) * 2048;
            *reinterpret_cast<unsigned*>(xr + u0g) = uhi;
            *reinterpret_cast<unsigned*>(xr + 1024 + u0g) = ulo;
        }
        grid_barrier(mygen);
    }

    *reinterpret_cast<float2*>(dh + b * HS + u0g) = h2;
    *reinterpret_cast<float2*>(dc + b * HS + u0g) = c2;
}

// =================================================================================
extern "C" void kernel_launch(void* const* d_in, const int* in_sizes, int n_in,
                              void* d_out, int out_size)
{
    const float* x   = (const float*)d_in[0];
    const float* U0  = (const float*)d_in[1];
    const float* V0  = (const float*)d_in[2];
    const float* bi0 = (const float*)d_in[3];
    const float* bh0 = (const float*)d_in[4];
    const float* U1  = (const float*)d_in[5];
    const float* V1  = (const float*)d_in[6];
    const float* bi1 = (const float*)d_in[7];
    const float* bh1 = (const float*)d_in[8];
    float* out = (float*)d_out;

    cudaFuncSetAttribute(k_inproj_t, cudaFuncAttributeMaxDynamicSharedMemorySize, SMEM_INPROJ);
    cudaFuncSetAttribute(k_layer_t,  cudaFuncAttributeMaxDynamicSharedMemorySize, SMEM_LAYER);

    float *pre = nullptr;
    bf16 *xs = nullptr, *us0 = nullptr, *vs0 = nullptr, *us1 = nullptr, *vs1 = nullptr;
    cudaGetSymbolAddress((void**)&pre, g_pre);
    cudaGetSymbolAddress((void**)&xs,  g_xs);
    cudaGetSymbolAddress((void**)&us0, g_Us0);
    cudaGetSymbolAddress((void**)&vs0, g_Vs0);
    cudaGetSymbolAddress((void**)&us1, g_Us1);
    cudaGetSymbolAddress((void**)&vs1, g_Vs1);

    const size_t O_OUT = (size_t)SEQ * BATCH * HS;
    const size_t BH    = (size_t)BATCH * HS;

    k_split_x<<<(MROWS * HS) / 256, 256>>>(x);
    {
        dim3 gsw((NG * HS) / 256, 4);
        k_split_w4<<<gsw, 256>>>(U0, V0, U1, V1, us0, vs0, us1, vs1);
    }

    const dim3 gIn(NG / 128, MROWS / 128);   // (32, 256)

    // layer 0 (h splits feed layer-1 inproj via g_xs)
    k_inproj_t<<<gIn, 256, SMEM_INPROJ>>>(xs, us0, pre);
    k_layer_t<<<NB_PERS, 256, SMEM_LAYER>>>(vs0, pre, bi0, bh0, nullptr, xs,
                                            out + O_OUT,            // h_f[0]
                                            out + O_OUT + 2 * BH);  // c_f[0]

    // layer 1
    k_inproj_t<<<gIn, 256, SMEM_INPROJ>>>(xs, us1, pre);
    k_layer_t<<<NB_PERS, 256, SMEM_LAYER>>>(vs1, pre, bi1, bh1, out, nullptr,
                                            out + O_OUT + BH,       // h_f[1]
                                            out + O_OUT + 3 * BH);  // c_f[1]
}

// round 7
// speedup vs baseline: 2.4172x; 1.0042x over previous
#include <cuda_runtime.h>
#include <cuda_bf16.h>
#include <cstdint>
#include <cstddef>

#define SEQ   512
#define BATCH 64
#define HS    1024
#define NG    4096
#define MROWS (SEQ*BATCH)     // 32768
#define NB_PERS 128
#define UNITS 8               // hidden units per CTA
#define GP 36                 // padded gate-smem row stride (floats)
#define HB (BATCH*2*HS)       // one h buffer (hi|lo), elements
#define SMEM_LAYER (1024 + 131072 + 32768 + 9216 + 256)
#define NCHUNK 32             // inproj k-chunks of 32
#define SMEM_INPROJ (3*32768 + 1024)

typedef unsigned long long u64;
typedef __nv_bfloat16 bf16;

// ---------------- static device scratch ----------------
__device__ float g_pre[(size_t)MROWS * NG];          // gate pre-activations (permuted cols)
__device__ bf16  g_xs[(size_t)MROWS * 2 * HS];       // input splits (hi|lo); layer0 h splits
__device__ bf16  g_hs[2 * HB];                       // double-buffered h splits
__device__ bf16  g_Us0[(size_t)NG * 2 * HS];         // permuted weight splits
__device__ bf16  g_Vs0[(size_t)NG * 2 * HS];
__device__ bf16  g_Us1[(size_t)NG * 2 * HS];
__device__ bf16  g_Vs1[(size_t)NG * 2 * HS];

// ---------------- grid barrier (release/acquire, monotonic gen) ----------------
__device__ unsigned g_cnt = 0;
__device__ unsigned g_gen = 0;

__device__ __forceinline__ void grid_barrier(unsigned& mygen) {
    __syncthreads();
    if (threadIdx.x == 0) {
        unsigned old;
        asm volatile("atom.add.acq_rel.gpu.u32 %0, [%1], 1;"
                     : "=r"(old) : "l"(&g_cnt) : "memory");
        if (old == (unsigned)(NB_PERS - 1)) {
            asm volatile("st.relaxed.gpu.u32 [%0], 0;" :: "l"(&g_cnt) : "memory");
            asm volatile("red.release.gpu.add.u32 [%0], 1;" :: "l"(&g_gen) : "memory");
        } else {
            unsigned cur;
            do {
                __nanosleep(20);
                asm volatile("ld.acquire.gpu.u32 %0, [%1];"
                             : "=r"(cur) : "l"(&g_gen) : "memory");
            } while (cur == mygen);
        }
    }
    mygen += 1;
    __syncthreads();
}

// ---------------- mma.sync building blocks (validated R4-R6) ----------------
__device__ __forceinline__ uint32_t smem_u32(const void* p) {
    uint32_t a;
    asm("{ .reg .u64 t; cvta.to.shared.u64 t, %1; cvt.u32.u64 %0, t; }" : "=r"(a) : "l"(p));
    return a;
}
__device__ __forceinline__ void ldsm4(uint32_t* f, uint32_t addr) {
    asm volatile("ldmatrix.sync.aligned.m8n8.x4.shared.b16 {%0,%1,%2,%3}, [%4];"
        : "=r"(f[0]), "=r"(f[1]), "=r"(f[2]), "=r"(f[3]) : "r"(addr));
}
__device__ __forceinline__ void mma16816(float* d, const uint32_t* a, uint32_t b0, uint32_t b1) {
    asm volatile("mma.sync.aligned.m16n8k16.row.col.f32.bf16.bf16.f32 "
        "{%0,%1,%2,%3}, {%4,%5,%6,%7}, {%8,%9}, {%0,%1,%2,%3};"
        : "+f"(d[0]), "+f"(d[1]), "+f"(d[2]), "+f"(d[3])
        : "r"(a[0]), "r"(a[1]), "r"(a[2]), "r"(a[3]), "r"(b0), "r"(b1));
}
__device__ __forceinline__ uint32_t swz(uint32_t r, uint32_t c16) {
    return r * 128u + ((c16 ^ (r & 7u)) << 4);
}
__device__ __forceinline__ uint32_t a_addr(uint32_t base, int lane, int m0, int k0) {
    int sel = lane >> 3;
    uint32_t row = (uint32_t)(m0 + (lane & 7) + ((sel & 1) << 3));
    uint32_t c16 = (uint32_t)((k0 >> 3) + (sel >> 1));
    return base + swz(row, c16);
}
__device__ __forceinline__ uint32_t b_addr(uint32_t base, int lane, int n0, int k0) {
    int sel = lane >> 3;
    uint32_t row = (uint32_t)(n0 + (lane & 7) + ((sel >> 1) << 3));
    uint32_t c16 = (uint32_t)((k0 >> 3) + (sel & 1));
    return base + swz(row, c16);
}
__device__ __forceinline__ void cp16(uint32_t dst, const void* src) {
    asm volatile("cp.async.cg.shared.global [%0], [%1], 16;" :: "r"(dst), "l"(src));
}

// load a [rows x 64] bf16 tile (row stride ld elems) into swizzled smem (sync path)
__device__ __forceinline__ void load_tile(uint32_t sdst, const bf16* __restrict__ src,
                                          int rows, int ld) {
    const int chunks = rows * 8;
    for (int i = threadIdx.x; i < chunks; i += 256) {
        int r = i >> 3, c = i & 7;
        const uint4* p = reinterpret_cast<const uint4*>(src + (size_t)r * ld + c * 8);
        uint4 v = __ldg(p);
        asm volatile("st.shared.v4.b32 [%0], {%1,%2,%3,%4};"
                     :: "r"(sdst + swz((uint32_t)r, (uint32_t)c)),
                        "r"(v.x), "r"(v.y), "r"(v.z), "r"(v.w));
    }
}
// async stage of a combined [128 x 64] tile: cols 0-31 = hi k-chunk, 32-63 = lo.
// src points at the hi row base (k offset applied); lo is +1024 elems.
__device__ __forceinline__ void stage_tile_hilo(uint32_t sdst, const bf16* __restrict__ src) {
    const int tid = threadIdx.x;
#pragma unroll
    for (int q = 0; q < 4; q++) {
        int i = tid + q * 256;               // 0..1023
        int r = i >> 3, c = i & 7;
        const bf16* s = src + (size_t)r * 2048 + (c < 4 ? c * 8 : 1024 + (c - 4) * 8);
        cp16(sdst + swz((uint32_t)r, (uint32_t)c), s);
    }
}

// ---------------- activations ----------------
__device__ __forceinline__ float sigmoid_acc(float x) {
    return 1.0f / (1.0f + __expf(-x));
}
__device__ __forceinline__ float tanh_acc(float x) {
    float e = __expf(-2.0f * fabsf(x));
    float t = (1.0f - e) / (1.0f + e);
    return copysignf(t, x);
}
__device__ __forceinline__ void split2(float v, bf16& hi, bf16& lo) {
    hi = __float2bfloat16(v);
    lo = __float2bfloat16(v - __bfloat162float(hi));
}

// =================================================================================
// split kernels. Weight rows gate-permuted: orig row r = g*1024+u -> 4u+g.
// =================================================================================
__global__ __launch_bounds__(256) void k_split_x(const float* __restrict__ x) {
    size_t i = (size_t)blockIdx.x * 256 + threadIdx.x;
    size_t m = i >> 10, k = i & 1023;
    bf16 hi, lo; split2(x[i], hi, lo);
    g_xs[m * 2048 + k]        = hi;
    g_xs[m * 2048 + 1024 + k] = lo;
}
__global__ __launch_bounds__(256) void k_split_w4(
    const float* __restrict__ W0, const float* __restrict__ W1,
    const float* __restrict__ W2, const float* __restrict__ W3,
    bf16* __restrict__ d0, bf16* __restrict__ d1,
    bf16* __restrict__ d2, bf16* __restrict__ d3)
{
    const float* W; bf16* dst;
    switch (blockIdx.y) {
        case 0:  W = W0; dst = d0; break;
        case 1:  W = W1; dst = d1; break;
        case 2:  W = W2; dst = d2; break;
        default: W = W3; dst = d3; break;
    }
    size_t i = (size_t)blockIdx.x * 256 + threadIdx.x;
    size_t n = i >> 10, k = i & 1023;
    size_t gidx = n >> 10, u = n & 1023;
    size_t np = u * 4 + gidx;
    bf16 hi, lo; split2(W[i], hi, lo);
    dst[np * 2048 + k]        = hi;
    dst[np * 2048 + 1024 + k] = lo;
}

// =================================================================================
// Input projection, 3-stage cp.async pipeline, 2 CTAs/SM.
// Stage = {A_hilo 128x64, B_hilo 128x64} = 32KB; K-chunk 32; 32 chunks.
// hi split at tile cols 0-31 (k0 0/16), lo at cols 32-63 (k0+32).
// =================================================================================
__global__ __launch_bounds__(256, 2) void k_inproj_t(
    const bf16* __restrict__ A, const bf16* __restrict__ W,
    float* __restrict__ C)
{
    extern __shared__ char dsm[];
    const uint32_t sbase = (smem_u32(dsm) + 1023u) & ~1023u;
    const int tid = threadIdx.x, wid = tid >> 5, lane = tid & 31;
    const int m0 = blockIdx.y * 128, n0 = blockIdx.x * 128;
    const int mi = wid & 3, ni = wid >> 2;

    const bf16* Arow = A + (size_t)m0 * 2048;
    const bf16* Wrow = W + (size_t)n0 * 2048;

    auto issue_stage = [&](int kb) {
        const uint32_t st = sbase + (uint32_t)(kb % 3) * 32768u;
        stage_tile_hilo(st,          Arow + kb * 32);
        stage_tile_hilo(st + 16384u, Wrow + kb * 32);
        asm volatile("cp.async.commit_group;");
    };

    float acc[2][8][4];
#pragma unroll
    for (int a = 0; a < 2; a++)
#pragma unroll
        for (int b = 0; b < 8; b++)
#pragma unroll
            for (int cpos = 0; cpos < 4; cpos++) acc[a][b][cpos] = 0.f;

    issue_stage(0);
    issue_stage(1);

#pragma unroll 1
    for (int kb = 0; kb < NCHUNK; kb++) {
        if (kb == NCHUNK - 1) asm volatile("cp.async.wait_group 0;");
        else                  asm volatile("cp.async.wait_group 1;");
        __syncthreads();
        if (kb + 2 < NCHUNK) issue_stage(kb + 2);

        const uint32_t st = sbase + (uint32_t)(kb % 3) * 32768u;
        const uint32_t sA = st, sB = st + 16384u;
#pragma unroll
        for (int ks = 0; ks < 2; ks++) {
            const int k0 = ks * 16;
            uint32_t ah[2][4], al[2][4];
#pragma unroll
            for (int mf = 0; mf < 2; mf++) {
                ldsm4(ah[mf], a_addr(sA, lane, mi * 32 + mf * 16, k0));
                ldsm4(al[mf], a_addr(sA, lane, mi * 32 + mf * 16, k0 + 32));
            }
#pragma unroll
            for (int np = 0; np < 4; np++) {
                const int nt = ni * 64 + np * 16;
                uint32_t bh[4], bl[4];
                ldsm4(bh, b_addr(sB, lane, nt, k0));
#pragma unroll
                for (int mf = 0; mf < 2; mf++) {
                    mma16816(acc[mf][np * 2],     ah[mf], bh[0], bh[1]);
                    mma16816(acc[mf][np * 2 + 1], ah[mf], bh[2], bh[3]);
                    mma16816(acc[mf][np * 2],     al[mf], bh[0], bh[1]);
                    mma16816(acc[mf][np * 2 + 1], al[mf], bh[2], bh[3]);
                }
                ldsm4(bl, b_addr(sB, lane, nt, k0 + 32));
#pragma unroll
                for (int mf = 0; mf < 2; mf++) {
                    mma16816(acc[mf][np * 2],     ah[mf], bl[0], bl[1]);
                    mma16816(acc[mf][np * 2 + 1], ah[mf], bl[2], bl[3]);
                }
            }
        }
    }

    const int r = lane >> 2, cq = (lane & 3) * 2;
#pragma unroll
    for (int mf = 0; mf < 2; mf++) {
#pragma unroll
        for (int nf = 0; nf < 8; nf++) {
            const int ncol = n0 + ni * 64 + nf * 8 + cq;
            const int row0 = m0 + mi * 32 + mf * 16 + r;
            *reinterpret_cast<float2*>(C + (size_t)row0 * NG + ncol) =
                make_float2(acc[mf][nf][0], acc[mf][nf][1]);
            *reinterpret_cast<float2*>(C + (size_t)(row0 + 8) * NG + ncol) =
                make_float2(acc[mf][nf][2], acc[mf][nf][3]);
        }
    }
}

// =================================================================================
// Persistent LSTM layer (unchanged from R6 — known good).
// =================================================================================
__global__ __launch_bounds__(256) void k_layer_t(
    const bf16* __restrict__ Vs, const float* __restrict__ pre,
    const float* __restrict__ b1, const float* __restrict__ b2,
    float* __restrict__ outbuf, bf16* __restrict__ xsplit,
    float* __restrict__ dh, float* __restrict__ dc)
{
    extern __shared__ char dsm[];
    const uint32_t sbase = (smem_u32(dsm) + 1023u) & ~1023u;
    const uint32_t sV = sbase;
    const uint32_t sA = sbase + 131072;
    const uint32_t sG = sbase + 131072 + 32768;
    const int tid = threadIdx.x, wid = tid >> 5, lane = tid & 31;
    const int bx = blockIdx.x;
    const int mi = wid & 3, ni = wid >> 2;
    const int b  = tid >> 2;
    const int ul = (tid & 3) * 2;
    const int u0g = bx * UNITS + ul;
    const int col0 = bx * 32 + 4 * ul;

    for (int s = 0; s < 2; s++)
        for (int kb = 0; kb < 16; kb++)
            load_tile(sV + (uint32_t)(s * 16 + kb) * 4096u,
                      Vs + (size_t)(bx * 32) * 2048 + s * 1024 + kb * 64,
                      32, 2048);

    float bias[8];
#pragma unroll
    for (int j = 0; j < 8; j++) {
        int n = col0 + j;
        int orig = ((n & 3) << 10) + (n >> 2);
        bias[j] = __ldg(b1 + orig) + __ldg(b2 + orig);
    }

    unsigned mygen;
    asm volatile("ld.relaxed.gpu.u32 %0, [%1];" : "=r"(mygen) : "l"(&g_gen));

    float2 c2 = make_float2(0.f, 0.f), h2 = make_float2(0.f, 0.f);
    __stcg(reinterpret_cast<unsigned*>(g_hs + (size_t)HB + b * 2048 + u0g), 0u);
    __stcg(reinterpret_cast<unsigned*>(g_hs + (size_t)HB + b * 2048 + 1024 + u0g), 0u);
    grid_barrier(mygen);

    for (int t = 0; t < SEQ; t++) {
        const bf16* hsrc = g_hs + (size_t)((t + 1) & 1) * HB;

        const float* prow = pre + ((size_t)t * BATCH + b) * NG + col0;
        float4 p0 = __ldg(reinterpret_cast<const float4*>(prow));
        float4 p1 = __ldg(reinterpret_cast<const float4*>(prow + 4));

#pragma unroll
        for (int s = 0; s < 2; s++) {
            uint32_t td = sA + (uint32_t)s * 8192u;
            const bf16* src = hsrc + s * 1024;
#pragma unroll
            for (int q = 0; q < 2; q++) {
                int i = tid + q * 256;
                int r = i >> 3, c = i & 7;
                cp16(td + swz(r, c), src + (size_t)r * 2048 + c * 8);
            }
        }
        asm volatile("cp.async.commit_group;");

        float acc[2][4];
#pragma unroll
        for (int f = 0; f < 2; f++)
#pragma unroll
            for (int j = 0; j < 4; j++) acc[f][j] = 0.f;

#pragma unroll 1
        for (int kb = 0; kb < 16; kb++) {
            asm volatile("cp.async.wait_group 0;");
            __syncthreads();
            if (kb < 15) {
                uint32_t bufn = (uint32_t)((kb + 1) & 1) * 16384u;
#pragma unroll
                for (int s = 0; s < 2; s++) {
                    uint32_t td = sA + bufn + (uint32_t)s * 8192u;
                    const bf16* src = hsrc + s * 1024 + (kb + 1) * 64;
#pragma unroll
                    for (int q = 0; q < 2; q++) {
                        int i = tid + q * 256;
                        int r = i >> 3, c = i & 7;
                        cp16(td + swz(r, c), src + (size_t)r * 2048 + c * 8);
                    }
                }
                asm volatile("cp.async.commit_group;");
            }
            const uint32_t ahB = sA + (uint32_t)(kb & 1) * 16384u;
            const uint32_t alB = ahB + 8192u;
            const uint32_t vhB = sV + (uint32_t)kb * 4096u;
            const uint32_t vlB = sV + (uint32_t)(16 + kb) * 4096u;
#pragma unroll
            for (int kst = 0; kst < 4; kst++) {
                const int k0 = kst * 16;
                uint32_t ah[4], al[4], bh[4], bl[4];
                ldsm4(ah, a_addr(ahB, lane, mi * 16, k0));
                ldsm4(bh, b_addr(vhB, lane, ni * 16, k0));
                ldsm4(al, a_addr(alB, lane, mi * 16, k0));
                ldsm4(bl, b_addr(vlB, lane, ni * 16, k0));
                mma16816(acc[0], ah, bh[0], bh[1]);
                mma16816(acc[1], ah, bh[2], bh[3]);
                mma16816(acc[0], al, bh[0], bh[1]);
                mma16816(acc[1], al, bh[2], bh[3]);
                mma16816(acc[0], ah, bl[0], bl[1]);
                mma16816(acc[1], ah, bl[2], bl[3]);
            }
        }

        {
            const int r = lane >> 2, cq = (lane & 3) * 2;
            const int row = mi * 16 + r;
#pragma unroll
            for (int f = 0; f < 2; f++) {
                const int col = ni * 16 + f * 8 + cq;
                asm volatile("st.shared.v2.f32 [%0], {%1,%2};"
                    :: "r"(sG + (uint32_t)(row * GP + col) * 4u), "f"(acc[f][0]), "f"(acc[f][1]));
                asm volatile("st.shared.v2.f32 [%0], {%1,%2};"
                    :: "r"(sG + (uint32_t)((row + 8) * GP + col) * 4u), "f"(acc[f][2]), "f"(acc[f][3]));
            }
        }
        __syncthreads();

        float4 ga, gb;
        asm volatile("ld.shared.v4.f32 {%0,%1,%2,%3}, [%4];"
            : "=f"(ga.x), "=f"(ga.y), "=f"(ga.z), "=f"(ga.w)
            : "r"(sG + (uint32_t)(b * GP + 4 * ul) * 4u));
        asm volatile("ld.shared.v4.f32 {%0,%1,%2,%3}, [%4];"
            : "=f"(gb.x), "=f"(gb.y), "=f"(gb.z), "=f"(gb.w)
            : "r"(sG + (uint32_t)(b * GP + 4 * ul + 4) * 4u));
        {
            float iv = sigmoid_acc(ga.x + p0.x + bias[0]);
            float fv = sigmoid_acc(ga.y + p0.y + bias[1]);
            float gv = tanh_acc   (ga.z + p0.z + bias[2]);
            float ov = sigmoid_acc(ga.w + p0.w + bias[3]);
            c2.x = fv * c2.x + iv * gv;
            h2.x = ov * tanh_acc(c2.x);
        }
        {
            float iv = sigmoid_acc(gb.x + p1.x + bias[4]);
            float fv = sigmoid_acc(gb.y + p1.y + bias[5]);
            float gv = tanh_acc   (gb.z + p1.z + bias[6]);
            float ov = sigmoid_acc(gb.w + p1.w + bias[7]);
            c2.y = fv * c2.y + iv * gv;
            h2.y = ov * tanh_acc(c2.y);
        }

        bf16 xh, xl, yh, yl;
        split2(h2.x, xh, xl);
        split2(h2.y, yh, yl);
        __nv_bfloat162 vhi = __halves2bfloat162(xh, yh);
        __nv_bfloat162 vlo = __halves2bfloat162(xl, yl);
        unsigned uhi = *reinterpret_cast<unsigned*>(&vhi);
        unsigned ulo = *reinterpret_cast<unsigned*>(&vlo);
        bf16* wdst = g_hs + (size_t)(t & 1) * HB + b * 2048;
        __stcg(reinterpret_cast<unsigned*>(wdst + u0g), uhi);
        __stcg(reinterpret_cast<unsigned*>(wdst + 1024 + u0g), ulo);
        if (outbuf)
            *reinterpret_cast<float2*>(outbuf + ((size_t)t * BATCH + b) * HS + u0g) = h2;
        if (xsplit) {
            bf16* xr = xsplit + ((size_t)t * BATCH + b) * 2048;
            *reinterpret_cast<unsigned*>(xr + u0g) = uhi;
            *reinterpret_cast<unsigned*>(xr + 1024 + u0g) = ulo;
        }
        grid_barrier(mygen);
    }

    *reinterpret_cast<float2*>(dh + b * HS + u0g) = h2;
    *reinterpret_cast<float2*>(dc + b * HS + u0g) = c2;
}

// =================================================================================
extern "C" void kernel_launch(void* const* d_in, const int* in_sizes, int n_in,
                              void* d_out, int out_size)
{
    const float* x   = (const float*)d_in[0];
    const float* U0  = (const float*)d_in[1];
    const float* V0  = (const float*)d_in[2];
    const float* bi0 = (const float*)d_in[3];
    const float* bh0 = (const float*)d_in[4];
    const float* U1  = (const float*)d_in[5];
    const float* V1  = (const float*)d_in[6];
    const float* bi1 = (const float*)d_in[7];
    const float* bh1 = (const float*)d_in[8];
    float* out = (float*)d_out;

    cudaFuncSetAttribute(k_inproj_t, cudaFuncAttributeMaxDynamicSharedMemorySize, SMEM_INPROJ);
    cudaFuncSetAttribute(k_layer_t,  cudaFuncAttributeMaxDynamicSharedMemorySize, SMEM_LAYER);

    float *pre = nullptr;
    bf16 *xs = nullptr, *us0 = nullptr, *vs0 = nullptr, *us1 = nullptr, *vs1 = nullptr;
    cudaGetSymbolAddress((void**)&pre, g_pre);
    cudaGetSymbolAddress((void**)&xs,  g_xs);
    cudaGetSymbolAddress((void**)&us0, g_Us0);
    cudaGetSymbolAddress((void**)&vs0, g_Vs0);
    cudaGetSymbolAddress((void**)&us1, g_Us1);
    cudaGetSymbolAddress((void**)&vs1, g_Vs1);

    const size_t O_OUT = (size_t)SEQ * BATCH * HS;
    const size_t BH    = (size_t)BATCH * HS;

    k_split_x<<<(MROWS * HS) / 256, 256>>>(x);
    {
        dim3 gsw((NG * HS) / 256, 4);
        k_split_w4<<<gsw, 256>>>(U0, V0, U1, V1, us0, vs0, us1, vs1);
    }

    const dim3 gIn(NG / 128, MROWS / 128);   // (32, 256)

    // layer 0 (h splits feed layer-1 inproj via g_xs)
    k_inproj_t<<<gIn, 256, SMEM_INPROJ>>>(xs, us0, pre);
    k_layer_t<<<NB_PERS, 256, SMEM_LAYER>>>(vs0, pre, bi0, bh0, nullptr, xs,
                                            out + O_OUT,            // h_f[0]
                                            out + O_OUT + 2 * BH);  // c_f[0]

    // layer 1
    k_inproj_t<<<gIn, 256, SMEM_INPROJ>>>(xs, us1, pre);
    k_layer_t<<<NB_PERS, 256, SMEM_LAYER>>>(vs1, pre, bi1, bh1, out, nullptr,
                                            out + O_OUT + BH,       // h_f[1]
                                            out + O_OUT + 3 * BH);  // c_f[1]
}